// round 14
// baseline (speedup 1.0000x reference)
#include <cuda_runtime.h>
#include <cuda_bf16.h>
#include <math.h>
#include <stdint.h>

#define BATCH 256
#define TSEQ  96
#define PRED  96
#define CIN   321
#define DM    512
#define G4    2048
#define HD    (BATCH*DM)
#define NSTEP (TSEQ+PRED-1)

#define AIMG  36864u
#define WIMG  9216u
#define XIMG  (24576u*144u)

__device__ float g_mean[BATCH*CIN];
__device__ float g_std [BATCH*CIN];
__device__ float g_istd[BATCH*CIN];
__device__ float g_Gx  [(size_t)BATCH*TSEQ*G4];
__device__ float g_Wd  [G4*DM];
__device__ float g_bd  [G4];
__device__ float g_benc[G4];
__device__ unsigned g_bar2[NSTEP*4*32];
__device__ __align__(1024) unsigned char g_Hbf[2*8*2*AIMG];
__device__ __align__(1024) float g_Hf32[2][BATCH][128];    // fp32 h, k in [384,512)
__device__ __align__(1024) unsigned char g_Dbf[(size_t)96*8*2*AIMG];
__device__ __align__(1024) unsigned char g_WTe[32*8*2*WIMG];
__device__ __align__(1024) unsigned char g_WTd[32*8*2*WIMG];
__device__ __align__(1024) unsigned char g_Xbf[6*2*XIMG];
__device__ __align__(1024) unsigned char g_WIe[32*6*2*WIMG];
__device__ __align__(1024) unsigned char g_WPe[6*8*2*WIMG];

typedef unsigned long long ull;
__device__ __forceinline__ float sigf(float x) { return 1.f / (1.f + expf(-x)); }
__device__ __forceinline__ float fsig(float x) { return __fdividef(1.f, 1.f + __expf(-x)); }
__device__ __forceinline__ float ftanh(float x) { return __fdividef(2.f, 1.f + __expf(-2.f * x)) - 1.f; }
__device__ __forceinline__ void fma2(ull& d, ull a, ull b) {
    asm("fma.rn.f32x2 %0, %1, %2, %0;" : "+l"(d) : "l"(a), "l"(b));
}
__device__ __forceinline__ float lo32(ull v) { return __uint_as_float((unsigned)v); }
__device__ __forceinline__ float hi32(ull v) { return __uint_as_float((unsigned)(v >> 32)); }
__device__ __forceinline__ uint32_t smem_u32(const void* p) {
    uint32_t a;
    asm("{ .reg .u64 t; cvta.to.shared.u64 t, %1; cvt.u32.u64 %0, t; }" : "=r"(a) : "l"(p));
    return a;
}
__device__ __forceinline__ void cpasync16(uint32_t dst, const void* src) {
    asm volatile("cp.async.cg.shared.global [%0], [%1], 16;" :: "r"(dst), "l"(src) : "memory");
}
#define CP_COMMIT() asm volatile("cp.async.commit_group;" ::: "memory")
#define CP_WAIT(N)  asm volatile("cp.async.wait_group %0;" :: "n"(N) : "memory")
__device__ __forceinline__ void ldsm4(uint32_t* r, uint32_t addr) {
    asm volatile("ldmatrix.sync.aligned.m8n8.x4.shared.b16 {%0,%1,%2,%3}, [%4];"
        : "=r"(r[0]), "=r"(r[1]), "=r"(r[2]), "=r"(r[3]) : "r"(addr));
}
__device__ __forceinline__ void mma16816(float* d, const uint32_t* a, const uint32_t* b) {
    asm volatile("mma.sync.aligned.m16n8k16.row.col.f32.bf16.bf16.f32 "
        "{%0,%1,%2,%3}, {%4,%5,%6,%7}, {%8,%9}, {%0,%1,%2,%3};"
        : "+f"(d[0]), "+f"(d[1]), "+f"(d[2]), "+f"(d[3])
        : "r"(a[0]), "r"(a[1]), "r"(a[2]), "r"(a[3]), "r"(b[0]), "r"(b[1]));
}
__device__ __forceinline__ void bfsplit2(float a, float b, uint32_t& hw, uint32_t& lw) {
    __nv_bfloat16 h0 = __float2bfloat16(a), h1 = __float2bfloat16(b);
    float r0 = a - __bfloat162float(h0), r1 = b - __bfloat162float(h1);
    __nv_bfloat16 l0 = __float2bfloat16(r0), l1 = __float2bfloat16(r1);
    hw = (uint32_t)__bfloat16_as_ushort(h0) | ((uint32_t)__bfloat16_as_ushort(h1) << 16);
    lw = (uint32_t)__bfloat16_as_ushort(l0) | ((uint32_t)__bfloat16_as_ushort(l1) << 16);
}

__global__ __launch_bounds__(256) void stats_kernel(const float* __restrict__ x) {
    int idx = blockIdx.x * 256 + threadIdx.x;
    if (idx >= BATCH * CIN) return;
    int b = idx / CIN, ch = idx % CIN;
    float s = 0.f, ss = 0.f;
    const float* p = x + (size_t)b * TSEQ * CIN + ch;
    #pragma unroll 4
    for (int t = 0; t < TSEQ; t++) { float v = p[t * CIN]; s += v; ss += v * v; }
    float mean = s * (1.f / TSEQ);
    float var = ss * (1.f / TSEQ) - mean * mean;
    if (var < 0.f) var = 0.f;
    float sd = sqrtf(var + 1e-5f);
    g_mean[idx] = mean; g_std[idx] = sd; g_istd[idx] = 1.f / sd;
}

__global__ __launch_bounds__(256) void bias_kernel(const float* __restrict__ bih,
                                                   const float* __restrict__ bhh,
                                                   const float* __restrict__ Wih,
                                                   const float* __restrict__ bp) {
    int n = blockIdx.x * 256 + threadIdx.x;
    if (n >= G4) return;
    float be = bih[n] + bhh[n];
    float s = 0.f;
    const float* w = Wih + (size_t)n * CIN;
    for (int j = 0; j < CIN; j++) s += w[j] * bp[j];
    g_benc[n] = be;
    g_bd[n] = be + s;
}

__global__ __launch_bounds__(256) void wd_kernel(const float* __restrict__ Wih,
                                                 const float* __restrict__ Wp,
                                                 const float* __restrict__ Whh) {
    __shared__ float As[64 * 17];
    __shared__ float Bs[16 * 65];
    int tid = threadIdx.x;
    int n0 = blockIdx.x * 64, m0 = blockIdx.y * 64;
    int tr = tid >> 4, tc = tid & 15;
    float acc[4][4] = {};
    for (int j0 = 0; j0 < CIN; j0 += 16) {
        #pragma unroll
        for (int i = 0; i < 4; i++) {
            int l = tid + 256 * i;
            int mr = l >> 4, jj = l & 15;
            int j = j0 + jj;
            As[mr * 17 + jj] = (j < CIN) ? Wih[(size_t)(m0 + mr) * CIN + j] : 0.f;
        }
        #pragma unroll
        for (int i = 0; i < 4; i++) {
            int l = tid + 256 * i;
            int jj = l >> 6, nr = l & 63;
            int j = j0 + jj;
            Bs[jj * 65 + nr] = (j < CIN) ? Wp[(size_t)j * DM + n0 + nr] : 0.f;
        }
        __syncthreads();
        #pragma unroll
        for (int jj = 0; jj < 16; jj++) {
            float a[4], bb[4];
            #pragma unroll
            for (int r = 0; r < 4; r++) a[r] = As[(tr * 4 + r) * 17 + jj];
            #pragma unroll
            for (int cc = 0; cc < 4; cc++) bb[cc] = Bs[jj * 65 + tc * 4 + cc];
            #pragma unroll
            for (int r = 0; r < 4; r++)
                #pragma unroll
                for (int cc = 0; cc < 4; cc++) acc[r][cc] += a[r] * bb[cc];
        }
        __syncthreads();
    }
    #pragma unroll
    for (int r = 0; r < 4; r++) {
        int m = m0 + tr * 4 + r;
        #pragma unroll
        for (int cc = 0; cc < 4; cc++) {
            int n = n0 + tc * 4 + cc;
            g_Wd[(size_t)m * DM + n] = Whh[(size_t)m * DM + n] + acc[r][cc];
        }
    }
}

__global__ __launch_bounds__(256) void wsplit_kernel(const float* __restrict__ src,
                                                     unsigned char* __restrict__ dst) {
    int chunk = blockIdx.x, ntile = blockIdx.y;
    int tid = threadIdx.x;
    int rr = tid >> 2, q = tid & 3;
    int joct = rr >> 5, rem = rr & 31;
    int gate = rem >> 3, j7 = rem & 7;
    int srow = gate * DM + ntile * 16 + joct * 8 + j7;
    unsigned char* d0 = dst + ((size_t)(ntile * 8 + chunk) * 2) * WIMG;
    #pragma unroll
    for (int c = 0; c < 18; c++) {
        int col = q * 18 + c;
        float v = (col < 64) ? src[(size_t)srow * DM + chunk * 64 + col] : 0.f;
        __nv_bfloat16 hb = __float2bfloat16(v);
        __nv_bfloat16 lb = __float2bfloat16(v - __bfloat162float(hb));
        size_t off = (size_t)rr * 144 + col * 2;
        *(__nv_bfloat16*)(d0 + off)        = hb;
        *(__nv_bfloat16*)(d0 + WIMG + off) = lb;
    }
}

__global__ __launch_bounds__(256) void wihsplit_kernel(const float* __restrict__ Wih) {
    int chunk = blockIdx.x, ntile = blockIdx.y;
    int tid = threadIdx.x;
    int rr = tid >> 2, q = tid & 3;
    int srow = ntile * 64 + rr;
    unsigned char* d0 = g_WIe + ((size_t)(ntile * 6 + chunk) * 2) * WIMG;
    #pragma unroll
    for (int c = 0; c < 18; c++) {
        int col = q * 18 + c;
        int k = chunk * 64 + col;
        float v = (col < 64 && k < CIN) ? Wih[(size_t)srow * CIN + k] : 0.f;
        __nv_bfloat16 hb = __float2bfloat16(v);
        __nv_bfloat16 lb = __float2bfloat16(v - __bfloat162float(hb));
        size_t off = (size_t)rr * 144 + col * 2;
        *(__nv_bfloat16*)(d0 + off)        = hb;
        *(__nv_bfloat16*)(d0 + WIMG + off) = lb;
    }
}

__global__ __launch_bounds__(256) void wpsplit_kernel(const float* __restrict__ Wp) {
    int chunk = blockIdx.x, ntile = blockIdx.y;
    int tid = threadIdx.x;
    int rr = tid >> 2, q = tid & 3;
    int n = ntile * 64 + rr;
    unsigned char* d0 = g_WPe + ((size_t)(ntile * 8 + chunk) * 2) * WIMG;
    #pragma unroll
    for (int c = 0; c < 18; c++) {
        int col = q * 18 + c;
        int k = chunk * 64 + col;
        float v = (col < 64 && n < CIN) ? Wp[(size_t)n * DM + k] : 0.f;
        __nv_bfloat16 hb = __float2bfloat16(v);
        __nv_bfloat16 lb = __float2bfloat16(v - __bfloat162float(hb));
        size_t off = (size_t)rr * 144 + col * 2;
        *(__nv_bfloat16*)(d0 + off)        = hb;
        *(__nv_bfloat16*)(d0 + WIMG + off) = lb;
    }
}

__global__ __launch_bounds__(256) void xsplit_kernel(const float* __restrict__ x) {
    int idx = blockIdx.x * 256 + threadIdx.x;
    if (idx >= BATCH * TSEQ * CIN) return;
    int m = idx / CIN, k = idx - m * CIN;
    int b = m / TSEQ;
    int bc = b * CIN + k;
    float v = (x[idx] - g_mean[bc]) * g_istd[bc];
    __nv_bfloat16 hb = __float2bfloat16(v);
    __nv_bfloat16 lb = __float2bfloat16(v - __bfloat162float(hb));
    int chunk = k >> 6, col = k & 63;
    size_t offh = ((size_t)(chunk * 2) * 24576 + m) * 144 + col * 2;
    *(__nv_bfloat16*)(g_Xbf + offh)        = hb;
    *(__nv_bfloat16*)(g_Xbf + offh + XIMG) = lb;
}

__global__ __launch_bounds__(256) void init_kernel() {
    int i = blockIdx.x * 256 + threadIdx.x;
    if (i < (int)(sizeof(g_Hbf) / 4)) ((uint32_t*)g_Hbf)[i] = 0u;
    if (i < (int)(sizeof(g_Hf32) / 4)) ((uint32_t*)g_Hf32)[i] = 0u;
    if (i < NSTEP * 4 * 32) g_bar2[i] = 0u;
}

// ---------------- gx = xnorm @ Wih^T via HMMA split ----------------------------
#define GXSTAGE 55296
#define GX_SMEM (2*GXSTAGE)
__global__ void __launch_bounds__(256, 1) gxmma_kernel() {
    extern __shared__ unsigned char smem[];
    const int tid = threadIdx.x;
    const int w = tid >> 5, lane = tid & 31;
    const int n0 = blockIdx.x * 64;
    const int m0 = blockIdx.y * 128;
    uint32_t sbase = smem_u32(smem);
    float acc[8][4];
    #pragma unroll
    for (int f = 0; f < 8; f++)
        #pragma unroll
        for (int r = 0; r < 4; r++) acc[f][r] = 0.f;

    const uint32_t aoff = (uint32_t)((w * 16 + (lane & 15)) * 144 + (lane >> 4) * 16);
    const uint32_t boff = (uint32_t)(((((lane >> 4) & 1) * 8) + (lane & 7)) * 144 + ((lane >> 3) & 1) * 16);
    const unsigned char* Bbase = g_WIe + ((size_t)blockIdx.x * 6 * 2) * WIMG;

    auto issue = [&](int chunk, int buf) {
        uint32_t sb = sbase + buf * GXSTAGE;
        #pragma unroll
        for (int i = 0; i < 14; i++) {
            int idx = tid + i * 256;
            if (idx >= 3456) break;
            uint32_t dst; const unsigned char* src;
            if (idx < 2304) {
                int sp = idx / 1152; int off = (idx - sp * 1152) * 16;
                dst = sb + sp * 18432 + off;
                src = g_Xbf + (size_t)(chunk * 2 + sp) * XIMG + (size_t)m0 * 144 + off;
            } else {
                int j = idx - 2304; int sp = j / 576; int off = (j - sp * 576) * 16;
                dst = sb + 36864 + sp * 9216 + off;
                src = Bbase + (size_t)(chunk * 2 + sp) * WIMG + off;
            }
            cpasync16(dst, src);
        }
        CP_COMMIT();
    };

    issue(0, 0); issue(1, 1);
    #pragma unroll 1
    for (int c = 0; c < 6; c++) {
        if (c < 5) { CP_WAIT(1); } else { CP_WAIT(0); }
        __syncthreads();
        uint32_t st = sbase + (c & 1) * GXSTAGE;
        uint32_t sAhi = st, sAlo = st + 18432, sWhi = st + 36864, sWlo = st + 46080;
        #pragma unroll
        for (int kf = 0; kf < 4; kf++) {
            uint32_t ah[4], al[4], bh[4][4], bl[4][4];
            ldsm4(ah, sAhi + aoff + kf * 32);
            ldsm4(al, sAlo + aoff + kf * 32);
            #pragma unroll
            for (int ng = 0; ng < 4; ng++) {
                ldsm4(bh[ng], sWhi + boff + ng * 2304 + kf * 32);
                ldsm4(bl[ng], sWlo + boff + ng * 2304 + kf * 32);
            }
            #pragma unroll
            for (int ng = 0; ng < 4; ng++) { mma16816(acc[2*ng], ah, bh[ng]); mma16816(acc[2*ng+1], ah, bh[ng]+2); }
            #pragma unroll
            for (int ng = 0; ng < 4; ng++) { mma16816(acc[2*ng], ah, bl[ng]); mma16816(acc[2*ng+1], ah, bl[ng]+2); }
            #pragma unroll
            for (int ng = 0; ng < 4; ng++) { mma16816(acc[2*ng], al, bh[ng]); mma16816(acc[2*ng+1], al, bh[ng]+2); }
        }
        __syncthreads();
        if (c + 2 < 6) issue(c + 2, c & 1);
    }
    #pragma unroll
    for (int f = 0; f < 8; f++) {
        int n = n0 + (f >> 1) * 16 + (f & 1) * 8 + (lane & 3) * 2;
        #pragma unroll
        for (int rowi = 0; rowi < 2; rowi++) {
            int m = m0 + w * 16 + (lane >> 2) + rowi * 8;
            *(float2*)&g_Gx[(size_t)m * G4 + n] = make_float2(acc[f][rowi*2], acc[f][rowi*2+1]);
        }
    }
}

// ---------------- persistent LSTM: HMMA(k<384) + FFMA2(k>=384) -----------------
#define SW_WH 0                       // 6 x 18432 = 110592
#define SW_AB 110592                  // 2 x 18432 = 36864
#define SW_WF 147456                  // 64 x 132 f32 = 33792
#define SW_HS 181248                  // 64 x 132 f32 = 33792
#define PERSIST_SMEM 215040

__global__ void __launch_bounds__(256, 1) persist_kernel(const float* __restrict__ gx,
                                                         const float* __restrict__ benc,
                                                         const float* __restrict__ bd,
                                                         const float* __restrict__ Whh,
                                                         const float* __restrict__ wdm) {
    extern __shared__ unsigned char smem[];
    const int tid = threadIdx.x;
    const int w = tid >> 5, lane = tid & 31;
    const int wr = w & 3, wc = w >> 2;
    const int ntile = blockIdx.x, mq = blockIdx.y;
    uint32_t sbase = smem_u32(smem);

    const uint32_t aoff = (uint32_t)((wr * 16 + (lane & 15)) * 144 + (lane >> 4) * 16);
    const uint32_t boff = (uint32_t)((wc * 32 + ((lane >> 4) & 1) * 8 + (lane & 7)) * 144 + ((lane >> 3) & 1) * 16);

    const unsigned char* WEsrc = g_WTe + ((size_t)(ntile * 8) * 2) * WIMG;
    const unsigned char* WDsrc = g_WTd + ((size_t)(ntile * 8) * 2) * WIMG;

    auto loadW = [&](const unsigned char* src) {   // 6 chunks only
        #pragma unroll 1
        for (int i = 0; i < 27; i++) {
            int idx = tid + i * 256;
            if (idx < 6912) {
                int img = idx / 576;   // (chunk*2+split), chunk<6
                int off = (idx - img * 576) * 16;
                cpasync16(sbase + SW_WH + img * 9216 + off, src + (size_t)img * WIMG + off);
            }
        }
        CP_COMMIT();
    };
    auto loadWF = [&](const float* srcw) {         // fp32 W for k in [384,512)
        int gj = tid >> 2, q = tid & 3;
        int g = gj >> 4, jloc2 = gj & 15;
        int srow = g * DM + ntile * 16 + jloc2;
        const float* sp = srcw + (size_t)srow * DM + 384 + q * 32;
        float* dp = (float*)(smem + SW_WF) + gj * 132 + q * 32;
        #pragma unroll 4
        for (int kk = 0; kk < 32; kk++) dp[kk] = sp[kk];
    };
    auto loadA = [&](const unsigned char* Apar, int chunk, int buf) {
        #pragma unroll
        for (int i = 0; i < 5; i++) {
            int idx = tid + i * 256;
            if (idx < 1152) {
                int split = idx / 576;
                int off = (idx - split * 576) * 16;
                cpasync16(sbase + SW_AB + buf * 18432 + split * 9216 + off,
                          Apar + (size_t)(chunk * 2 + split) * AIMG + mq * 9216 + off);
            }
        }
        CP_COMMIT();
    };
    auto loadH = [&](const float* Hfp) {           // fp32 h rows for this mq
        #pragma unroll
        for (int i = 0; i < 8; i++) {
            int idx = tid + i * 256;
            int row = idx >> 5, seg = idx & 31;
            cpasync16(sbase + SW_HS + row * 528 + seg * 16,
                      Hfp + (size_t)(mq * 64 + row) * 128 + seg * 4);
        }
        CP_COMMIT();
    };

    const int j0 = ntile * 16 + wc * 8 + (lane & 3) * 2;
    const int jloc = wc * 8 + (lane & 3) * 2;
    const int rloc0 = wr * 16 + (lane >> 2);
    const int bbase = mq * 64 + rloc0;
    const int chunkA = ntile >> 2;
    const size_t colOff = (size_t)((ntile & 3) * 16 + jloc) * 2;

    float bi[4][2];
    #pragma unroll
    for (int g = 0; g < 4; g++) { bi[g][0] = benc[g * DM + j0]; bi[g][1] = benc[g * DM + j0 + 1]; }
    float creg[4] = {0.f, 0.f, 0.f, 0.f};

    loadW(WEsrc);
    loadWF(Whh);
    CP_WAIT(0);
    __syncthreads();

    for (int s = 0; s < NSTEP; s++) {
        const bool enc = (s < TSEQ);
        if (s == TSEQ) {
            __syncthreads();
            loadW(WDsrc);
            loadWF(wdm);
            #pragma unroll
            for (int g = 0; g < 4; g++) { bi[g][0] = bd[g * DM + j0]; bi[g][1] = bd[g * DM + j0 + 1]; }
            CP_WAIT(0);
            __syncthreads();
        }
        const int par = s & 1;
        const unsigned char* Apar = g_Hbf + (size_t)(par * 16) * AIMG;

        float pr[16];
        if (enc) {
            #pragma unroll
            for (int rowi = 0; rowi < 2; rowi++) {
                const float* gr = gx + ((size_t)(bbase + rowi * 8) * TSEQ + s) * G4;
                #pragma unroll
                for (int g = 0; g < 4; g++) {
                    float2 v = *(const float2*)&gr[g * DM + j0];
                    pr[rowi * 8 + g * 2]     = v.x;
                    pr[rowi * 8 + g * 2 + 1] = v.y;
                }
            }
        }

        float acc[4][4];
        #pragma unroll
        for (int g = 0; g < 4; g++)
            #pragma unroll
            for (int r = 0; r < 4; r++) acc[g][r] = 0.f;
        ull f2[4][2][2];
        #pragma unroll
        for (int g = 0; g < 4; g++)
            #pragma unroll
            for (int r = 0; r < 2; r++) { f2[g][r][0] = 0ull; f2[g][r][1] = 0ull; }

        if (s > 0) {
            loadH(&g_Hf32[par][0][0]);    // group 1 (oldest)
            loadA(Apar, 0, 0);
            loadA(Apar, 1, 1);
            #pragma unroll 1
            for (int c = 0; c < 6; c++) {
                if (c < 5) { CP_WAIT(1); } else { CP_WAIT(0); }
                __syncthreads();
                uint32_t at = sbase + SW_AB + (c & 1) * 18432;
                uint32_t sAhi = at, sAlo = at + 9216;
                uint32_t wt = sbase + SW_WH + c * 18432;
                uint32_t sWhi = wt, sWlo = wt + 9216;
                #pragma unroll
                for (int kf = 0; kf < 4; kf++) {
                    uint32_t ah[4], al[4], bh0[4], bh1[4], bl0[4], bl1[4];
                    ldsm4(ah,  sAhi + aoff + kf * 32);
                    ldsm4(al,  sAlo + aoff + kf * 32);
                    ldsm4(bh0, sWhi + boff + kf * 32);
                    ldsm4(bh1, sWhi + boff + 2304 + kf * 32);
                    ldsm4(bl0, sWlo + boff + kf * 32);
                    ldsm4(bl1, sWlo + boff + 2304 + kf * 32);
                    mma16816(acc[0], ah, bh0); mma16816(acc[1], ah, bh0 + 2);
                    mma16816(acc[2], ah, bh1); mma16816(acc[3], ah, bh1 + 2);
                    mma16816(acc[0], ah, bl0); mma16816(acc[1], ah, bl0 + 2);
                    mma16816(acc[2], ah, bl1); mma16816(acc[3], ah, bl1 + 2);
                    mma16816(acc[0], al, bh0); mma16816(acc[1], al, bh0 + 2);
                    mma16816(acc[2], al, bh1); mma16816(acc[3], al, bh1 + 2);
                }
                // FFMA2 slice (k >= 384), interleaved with tensor work
                if (c >= 2) {
                    const float* hsp = (const float*)(smem + SW_HS);
                    const float* wfp = (const float*)(smem + SW_WF);
                    int kb = (c - 2) * 32;
                    #pragma unroll
                    for (int kp = 0; kp < 16; kp++) {
                        int kk = kb + kp * 2;
                        ull hp0 = *(const ull*)&hsp[rloc0 * 132 + kk];
                        ull hp1 = *(const ull*)&hsp[(rloc0 + 8) * 132 + kk];
                        #pragma unroll
                        for (int g = 0; g < 4; g++) {
                            ull w0 = *(const ull*)&wfp[(g * 16 + jloc) * 132 + kk];
                            ull w1 = *(const ull*)&wfp[(g * 16 + jloc + 1) * 132 + kk];
                            fma2(f2[g][0][0], hp0, w0); fma2(f2[g][0][1], hp0, w1);
                            fma2(f2[g][1][0], hp1, w0); fma2(f2[g][1][1], hp1, w1);
                        }
                    }
                }
                __syncthreads();
                if (c + 2 < 6) loadA(Apar, c + 2, c & 1);
            }
        }

        // ---- epilogue ----
        unsigned char* imgHi = g_Hbf + (size_t)(((par ^ 1) * 8 + chunkA) * 2) * AIMG;
        unsigned char* imgLo = imgHi + AIMG;
        float* Hout = &g_Hf32[par ^ 1][0][0];
        unsigned char* decHi = nullptr;
        if (s >= TSEQ - 1) {
            int d = s - (TSEQ - 1);
            decHi = g_Dbf + (size_t)((d * 8 + chunkA) * 2) * AIMG;
        }

        #pragma unroll
        for (int rowi = 0; rowi < 2; rowi++) {
            int b = bbase + rowi * 8;
            float h2[2];
            #pragma unroll
            for (int cp = 0; cp < 2; cp++) {
                float gi = acc[0][rowi * 2 + cp] + bi[0][cp] + lo32(f2[0][rowi][cp]) + hi32(f2[0][rowi][cp]);
                float gf = acc[1][rowi * 2 + cp] + bi[1][cp] + lo32(f2[1][rowi][cp]) + hi32(f2[1][rowi][cp]);
                float gg = acc[2][rowi * 2 + cp] + bi[2][cp] + lo32(f2[2][rowi][cp]) + hi32(f2[2][rowi][cp]);
                float go = acc[3][rowi * 2 + cp] + bi[3][cp] + lo32(f2[3][rowi][cp]) + hi32(f2[3][rowi][cp]);
                if (enc) {
                    gi += pr[rowi * 8 + 0 + cp];
                    gf += pr[rowi * 8 + 2 + cp];
                    gg += pr[rowi * 8 + 4 + cp];
                    go += pr[rowi * 8 + 6 + cp];
                }
                float cn = fsig(gf) * creg[rowi * 2 + cp] + fsig(gi) * ftanh(gg);
                float hn = fsig(go) * ftanh(cn);
                creg[rowi * 2 + cp] = cn;
                h2[cp] = hn;
            }
            uint32_t hw, lw;
            bfsplit2(h2[0], h2[1], hw, lw);
            size_t off = (size_t)b * 144 + colOff;
            *(uint32_t*)(imgHi + off) = hw;
            *(uint32_t*)(imgLo + off) = lw;
            if (ntile >= 24)
                *(float2*)&Hout[(size_t)b * 128 + (j0 - 384)] = make_float2(h2[0], h2[1]);
            if (decHi) {
                *(uint32_t*)(decHi + off) = hw;
                *(uint32_t*)(decHi + AIMG + off) = lw;
            }
        }

        if (s < NSTEP - 1) {
            __threadfence();
            __syncthreads();
            if (tid == 0) {
                unsigned* p = &g_bar2[(s * 4 + mq) * 32];
                unsigned prev = atomicAdd(p, 1u);
                if (prev != 31u) {
                    unsigned v;
                    do {
                        asm volatile("ld.acquire.gpu.u32 %0, [%1];" : "=r"(v) : "l"(p) : "memory");
                    } while (v < 32u);
                }
            }
            __syncthreads();
        }
    }
}

// ---------------- out: Y = Dbf @ Wp^T via HMMA ---------------------------------
#define OSTAGE 55296
#define OUT_SMEM (2*OSTAGE)
__global__ void __launch_bounds__(256, 1) outmma_kernel(const float* __restrict__ bp,
                                                        float* __restrict__ out) {
    extern __shared__ unsigned char smem[];
    const int tid = threadIdx.x;
    const int w = tid >> 5, lane = tid & 31;
    const int ntile = blockIdx.x;
    const int mt = blockIdx.y;
    const int d = mt >> 1, half = mt & 1;
    const int m0 = half * 128;
    uint32_t sbase = smem_u32(smem);
    float acc[8][4];
    #pragma unroll
    for (int f = 0; f < 8; f++)
        #pragma unroll
        for (int r = 0; r < 4; r++) acc[f][r] = 0.f;

    const uint32_t aoff = (uint32_t)((w * 16 + (lane & 15)) * 144 + (lane >> 4) * 16);
    const uint32_t boff = (uint32_t)(((((lane >> 4) & 1) * 8) + (lane & 7)) * 144 + ((lane >> 3) & 1) * 16);
    const unsigned char* Abase = g_Dbf + (size_t)(d * 16) * AIMG;
    const unsigned char* Bbase = g_WPe + ((size_t)(ntile * 8) * 2) * WIMG;

    auto issue = [&](int chunk, int buf) {
        uint32_t sb = sbase + buf * OSTAGE;
        #pragma unroll
        for (int i = 0; i < 14; i++) {
            int idx = tid + i * 256;
            if (idx >= 3456) break;
            uint32_t dst; const unsigned char* src;
            if (idx < 2304) {
                int sp = idx / 1152; int off = (idx - sp * 1152) * 16;
                dst = sb + sp * 18432 + off;
                src = Abase + (size_t)(chunk * 2 + sp) * AIMG + (size_t)m0 * 144 + off;
            } else {
                int j = idx - 2304; int sp = j / 576; int off = (j - sp * 576) * 16;
                dst = sb + 36864 + sp * 9216 + off;
                src = Bbase + (size_t)(chunk * 2 + sp) * WIMG + off;
            }
            cpasync16(dst, src);
        }
        CP_COMMIT();
    };

    issue(0, 0); issue(1, 1);
    #pragma unroll 1
    for (int c = 0; c < 8; c++) {
        if (c < 7) { CP_WAIT(1); } else { CP_WAIT(0); }
        __syncthreads();
        uint32_t st = sbase + (c & 1) * OSTAGE;
        uint32_t sAhi = st, sAlo = st + 18432, sWhi = st + 36864, sWlo = st + 46080;
        #pragma unroll
        for (int kf = 0; kf < 4; kf++) {
            uint32_t ah[4], al[4], bh[4][4], bl[4][4];
            ldsm4(ah, sAhi + aoff + kf * 32);
            ldsm4(al, sAlo + aoff + kf * 32);
            #pragma unroll
            for (int ng = 0; ng < 4; ng++) {
                ldsm4(bh[ng], sWhi + boff + ng * 2304 + kf * 32);
                ldsm4(bl[ng], sWlo + boff + ng * 2304 + kf * 32);
            }
            #pragma unroll
            for (int ng = 0; ng < 4; ng++) { mma16816(acc[2*ng], ah, bh[ng]); mma16816(acc[2*ng+1], ah, bh[ng]+2); }
            #pragma unroll
            for (int ng = 0; ng < 4; ng++) { mma16816(acc[2*ng], ah, bl[ng]); mma16816(acc[2*ng+1], ah, bl[ng]+2); }
            #pragma unroll
            for (int ng = 0; ng < 4; ng++) { mma16816(acc[2*ng], al, bh[ng]); mma16816(acc[2*ng+1], al, bh[ng]+2); }
        }
        __syncthreads();
        if (c + 2 < 8) issue(c + 2, c & 1);
    }
    #pragma unroll
    for (int f = 0; f < 8; f++) {
        int gn = ntile * 64 + (f >> 1) * 16 + (f & 1) * 8 + (lane & 3) * 2;
        #pragma unroll
        for (int rowi = 0; rowi < 2; rowi++) {
            int b = m0 + w * 16 + (lane >> 2) + rowi * 8;
            #pragma unroll
            for (int cp = 0; cp < 2; cp++) {
                int n = gn + cp;
                if (n < CIN) {
                    int bc = b * CIN + n;
                    float y = acc[f][rowi * 2 + cp] + bp[n];
                    out[(size_t)b * PRED * CIN + (size_t)d * CIN + n] =
                        y * g_std[bc] + g_mean[bc];
                }
            }
        }
    }
}

// ---------------- host launcher ------------------------------------------------
extern "C" void kernel_launch(void* const* d_in, const int* in_sizes, int n_in,
                              void* d_out, int out_size) {
    const float* x   = (const float*)d_in[0];
    const float* Wih = (const float*)d_in[1];
    const float* Whh = (const float*)d_in[2];
    const float* bih = (const float*)d_in[3];
    const float* bhh = (const float*)d_in[4];
    const float* Wp  = (const float*)d_in[5];
    const float* bp  = (const float*)d_in[6];
    float* out = (float*)d_out;

    float *gx, *wd, *bd, *benc;
    unsigned char *wte, *wtd;
    cudaGetSymbolAddress((void**)&gx,   g_Gx);
    cudaGetSymbolAddress((void**)&wd,   g_Wd);
    cudaGetSymbolAddress((void**)&bd,   g_bd);
    cudaGetSymbolAddress((void**)&benc, g_benc);
    cudaGetSymbolAddress((void**)&wte,  g_WTe);
    cudaGetSymbolAddress((void**)&wtd,  g_WTd);

    cudaFuncSetAttribute(persist_kernel, cudaFuncAttributeMaxDynamicSharedMemorySize, PERSIST_SMEM);
    cudaFuncSetAttribute(gxmma_kernel, cudaFuncAttributeMaxDynamicSharedMemorySize, GX_SMEM);
    cudaFuncSetAttribute(outmma_kernel, cudaFuncAttributeMaxDynamicSharedMemorySize, OUT_SMEM);

    stats_kernel<<<(BATCH * CIN + 255) / 256, 256>>>(x);
    bias_kernel<<<(G4 + 255) / 256, 256>>>(bih, bhh, Wih, bp);
    wd_kernel<<<dim3(DM / 64, G4 / 64), 256>>>(Wih, Wp, Whh);
    xsplit_kernel<<<(BATCH * TSEQ * CIN + 255) / 256, 256>>>(x);
    wihsplit_kernel<<<dim3(6, 32), 256>>>(Wih);
    wpsplit_kernel<<<dim3(8, 6), 256>>>(Wp);
    wsplit_kernel<<<dim3(8, 32), 256>>>(Whh, wte);
    wsplit_kernel<<<dim3(8, 32), 256>>>(wd, wtd);
    init_kernel<<<((int)(sizeof(g_Hbf) / 4) + 255) / 256, 256>>>();
    gxmma_kernel<<<dim3(32, 192), 256, GX_SMEM>>>();

    persist_kernel<<<dim3(32, 4), 256, PERSIST_SMEM>>>(gx, benc, bd, Whh, wd);

    outmma_kernel<<<dim3(6, 192), 256, OUT_SMEM>>>(bp, out);
    (void)in_sizes; (void)n_in; (void)out_size;
}

// round 15
// speedup vs baseline: 1.7149x; 1.7149x over previous
#include <cuda_runtime.h>
#include <cuda_fp16.h>
#include <math.h>
#include <stdint.h>

#define BATCH 256
#define TSEQ  96
#define PRED  96
#define CIN   321
#define DM    512
#define G4    2048
#define HD    (BATCH*DM)
#define NSTEP (TSEQ+PRED-1)

#define AIMG  36864u            // f16 image: 256 rows x 144 B per (chunk,split)
#define WIMG  9216u             // f16 W image: 64 rows x 144 B (single)
#define XIMG  (24576u*144u)

__device__ float g_mean[BATCH*CIN];
__device__ float g_std [BATCH*CIN];
__device__ float g_istd[BATCH*CIN];
__device__ float g_Gx  [(size_t)BATCH*TSEQ*G4];
__device__ float g_Wd  [G4*DM];
__device__ float g_bd  [G4];
__device__ float g_benc[G4];
__device__ unsigned g_bar2[NSTEP*4*32];
// f16 hidden images: [par2][chunk8][split2][256][72]
__device__ __align__(1024) unsigned char g_Hbf[2*8*2*AIMG];
// decoder hidden f16 split images: [d96][chunk8][split2][256][72]
__device__ __align__(1024) unsigned char g_Dbf[(size_t)96*8*2*AIMG];
// recurrent W images (single f16): [ntile32][chunk8][64][72]
__device__ __align__(1024) unsigned char g_WTe[32*8*WIMG];
__device__ __align__(1024) unsigned char g_WTd[32*8*WIMG];
// gx operand images: x f16 hi/lo, Wih single f16
__device__ __align__(1024) unsigned char g_Xbf[6*2*XIMG];
__device__ __align__(1024) unsigned char g_WIe[32*6*WIMG];
// Wp single f16: [ntile6][chunk8][64][72]
__device__ __align__(1024) unsigned char g_WPe[6*8*WIMG];

__device__ __forceinline__ float sigf(float x) { return 1.f / (1.f + expf(-x)); }
__device__ __forceinline__ float fsig(float x) { return __fdividef(1.f, 1.f + __expf(-x)); }
__device__ __forceinline__ float ftanh(float x) { return __fdividef(2.f, 1.f + __expf(-2.f * x)) - 1.f; }

__device__ __forceinline__ uint32_t smem_u32(const void* p) {
    uint32_t a;
    asm("{ .reg .u64 t; cvta.to.shared.u64 t, %1; cvt.u32.u64 %0, t; }" : "=r"(a) : "l"(p));
    return a;
}
__device__ __forceinline__ void cpasync16(uint32_t dst, const void* src) {
    asm volatile("cp.async.cg.shared.global [%0], [%1], 16;" :: "r"(dst), "l"(src) : "memory");
}
#define CP_COMMIT() asm volatile("cp.async.commit_group;" ::: "memory")
#define CP_WAIT(N)  asm volatile("cp.async.wait_group %0;" :: "n"(N) : "memory")

__device__ __forceinline__ void ldsm4(uint32_t* r, uint32_t addr) {
    asm volatile("ldmatrix.sync.aligned.m8n8.x4.shared.b16 {%0,%1,%2,%3}, [%4];"
        : "=r"(r[0]), "=r"(r[1]), "=r"(r[2]), "=r"(r[3]) : "r"(addr));
}
__device__ __forceinline__ void mma16816(float* d, const uint32_t* a, const uint32_t* b) {
    asm volatile("mma.sync.aligned.m16n8k16.row.col.f32.f16.f16.f32 "
        "{%0,%1,%2,%3}, {%4,%5,%6,%7}, {%8,%9}, {%0,%1,%2,%3};"
        : "+f"(d[0]), "+f"(d[1]), "+f"(d[2]), "+f"(d[3])
        : "r"(a[0]), "r"(a[1]), "r"(a[2]), "r"(a[3]), "r"(b[0]), "r"(b[1]));
}
// f16 hi/lo split of a float pair, packed
__device__ __forceinline__ void hfsplit2(float a, float b, uint32_t& hw, uint32_t& lw) {
    __half h0 = __float2half_rn(a), h1 = __float2half_rn(b);
    float r0 = a - __half2float(h0), r1 = b - __half2float(h1);
    __half l0 = __float2half_rn(r0), l1 = __float2half_rn(r1);
    hw = (uint32_t)__half_as_ushort(h0) | ((uint32_t)__half_as_ushort(h1) << 16);
    lw = (uint32_t)__half_as_ushort(l0) | ((uint32_t)__half_as_ushort(l1) << 16);
}

__global__ __launch_bounds__(256) void stats_kernel(const float* __restrict__ x) {
    int idx = blockIdx.x * 256 + threadIdx.x;
    if (idx >= BATCH * CIN) return;
    int b = idx / CIN, ch = idx % CIN;
    float s = 0.f, ss = 0.f;
    const float* p = x + (size_t)b * TSEQ * CIN + ch;
    #pragma unroll 4
    for (int t = 0; t < TSEQ; t++) { float v = p[t * CIN]; s += v; ss += v * v; }
    float mean = s * (1.f / TSEQ);
    float var = ss * (1.f / TSEQ) - mean * mean;
    if (var < 0.f) var = 0.f;
    float sd = sqrtf(var + 1e-5f);
    g_mean[idx] = mean; g_std[idx] = sd; g_istd[idx] = 1.f / sd;
}

__global__ __launch_bounds__(256) void bias_kernel(const float* __restrict__ bih,
                                                   const float* __restrict__ bhh,
                                                   const float* __restrict__ Wih,
                                                   const float* __restrict__ bp) {
    int n = blockIdx.x * 256 + threadIdx.x;
    if (n >= G4) return;
    float be = bih[n] + bhh[n];
    float s = 0.f;
    const float* w = Wih + (size_t)n * CIN;
    for (int j = 0; j < CIN; j++) s += w[j] * bp[j];
    g_benc[n] = be;
    g_bd[n] = be + s;
}

__global__ __launch_bounds__(256) void wd_kernel(const float* __restrict__ Wih,
                                                 const float* __restrict__ Wp,
                                                 const float* __restrict__ Whh) {
    __shared__ float As[64 * 17];
    __shared__ float Bs[16 * 65];
    int tid = threadIdx.x;
    int n0 = blockIdx.x * 64, m0 = blockIdx.y * 64;
    int tr = tid >> 4, tc = tid & 15;
    float acc[4][4] = {};
    for (int j0 = 0; j0 < CIN; j0 += 16) {
        #pragma unroll
        for (int i = 0; i < 4; i++) {
            int l = tid + 256 * i;
            int mr = l >> 4, jj = l & 15;
            int j = j0 + jj;
            As[mr * 17 + jj] = (j < CIN) ? Wih[(size_t)(m0 + mr) * CIN + j] : 0.f;
        }
        #pragma unroll
        for (int i = 0; i < 4; i++) {
            int l = tid + 256 * i;
            int jj = l >> 6, nr = l & 63;
            int j = j0 + jj;
            Bs[jj * 65 + nr] = (j < CIN) ? Wp[(size_t)j * DM + n0 + nr] : 0.f;
        }
        __syncthreads();
        #pragma unroll
        for (int jj = 0; jj < 16; jj++) {
            float a[4], bb[4];
            #pragma unroll
            for (int r = 0; r < 4; r++) a[r] = As[(tr * 4 + r) * 17 + jj];
            #pragma unroll
            for (int cc = 0; cc < 4; cc++) bb[cc] = Bs[jj * 65 + tc * 4 + cc];
            #pragma unroll
            for (int r = 0; r < 4; r++)
                #pragma unroll
                for (int cc = 0; cc < 4; cc++) acc[r][cc] += a[r] * bb[cc];
        }
        __syncthreads();
    }
    #pragma unroll
    for (int r = 0; r < 4; r++) {
        int m = m0 + tr * 4 + r;
        #pragma unroll
        for (int cc = 0; cc < 4; cc++) {
            int n = n0 + tc * 4 + cc;
            g_Wd[(size_t)m * DM + n] = Whh[(size_t)m * DM + n] + acc[r][cc];
        }
    }
}

// single f16 W image, gate-interleaved rows
__global__ __launch_bounds__(256) void wsplit_kernel(const float* __restrict__ src,
                                                     unsigned char* __restrict__ dst) {
    int chunk = blockIdx.x, ntile = blockIdx.y;
    int tid = threadIdx.x;
    int rr = tid >> 2, q = tid & 3;
    int joct = rr >> 5, rem = rr & 31;
    int gate = rem >> 3, j7 = rem & 7;
    int srow = gate * DM + ntile * 16 + joct * 8 + j7;
    unsigned char* d0 = dst + (size_t)(ntile * 8 + chunk) * WIMG;
    #pragma unroll
    for (int c = 0; c < 18; c++) {
        int col = q * 18 + c;
        float v = (col < 64) ? src[(size_t)srow * DM + chunk * 64 + col] : 0.f;
        *(__half*)(d0 + (size_t)rr * 144 + col * 2) = __float2half_rn(v);
    }
}

__global__ __launch_bounds__(256) void wihsplit_kernel(const float* __restrict__ Wih) {
    int chunk = blockIdx.x, ntile = blockIdx.y;
    int tid = threadIdx.x;
    int rr = tid >> 2, q = tid & 3;
    int srow = ntile * 64 + rr;
    unsigned char* d0 = g_WIe + (size_t)(ntile * 6 + chunk) * WIMG;
    #pragma unroll
    for (int c = 0; c < 18; c++) {
        int col = q * 18 + c;
        int k = chunk * 64 + col;
        float v = (col < 64 && k < CIN) ? Wih[(size_t)srow * CIN + k] : 0.f;
        if (col < 64 || v == 0.f)
            *(__half*)(d0 + (size_t)rr * 144 + col * 2) = __float2half_rn(v);
    }
}

__global__ __launch_bounds__(256) void wpsplit_kernel(const float* __restrict__ Wp) {
    int chunk = blockIdx.x, ntile = blockIdx.y;
    int tid = threadIdx.x;
    int rr = tid >> 2, q = tid & 3;
    int n = ntile * 64 + rr;
    unsigned char* d0 = g_WPe + (size_t)(ntile * 8 + chunk) * WIMG;
    #pragma unroll
    for (int c = 0; c < 18; c++) {
        int col = q * 18 + c;
        int k = chunk * 64 + col;
        float v = (col < 64 && n < CIN) ? Wp[(size_t)n * DM + k] : 0.f;
        *(__half*)(d0 + (size_t)rr * 144 + col * 2) = __float2half_rn(v);
    }
}

__global__ __launch_bounds__(256) void xsplit_kernel(const float* __restrict__ x) {
    int idx = blockIdx.x * 256 + threadIdx.x;
    if (idx >= BATCH * TSEQ * CIN) return;
    int m = idx / CIN, k = idx - m * CIN;
    int b = m / TSEQ;
    int bc = b * CIN + k;
    float v = (x[idx] - g_mean[bc]) * g_istd[bc];
    __half hb = __float2half_rn(v);
    __half lb = __float2half_rn(v - __half2float(hb));
    int chunk = k >> 6, col = k & 63;
    size_t offh = ((size_t)(chunk * 2) * 24576 + m) * 144 + col * 2;
    *(__half*)(g_Xbf + offh)        = hb;
    *(__half*)(g_Xbf + offh + XIMG) = lb;
}

__global__ __launch_bounds__(256) void init_kernel() {
    int i = blockIdx.x * 256 + threadIdx.x;
    if (i < (int)(sizeof(g_Hbf) / 4)) ((uint32_t*)g_Hbf)[i] = 0u;
    if (i < NSTEP * 4 * 32) g_bar2[i] = 0u;
}

// ---------------- gx = xnorm @ Wih^T, 2-term f16 -------------------------------
#define GXSTAGE 46080
#define GX_SMEM (2*GXSTAGE)
__global__ void __launch_bounds__(256, 1) gxmma_kernel() {
    extern __shared__ unsigned char smem[];
    const int tid = threadIdx.x;
    const int w = tid >> 5, lane = tid & 31;
    const int n0 = blockIdx.x * 64;
    const int m0 = blockIdx.y * 128;
    uint32_t sbase = smem_u32(smem);
    float acc[8][4];
    #pragma unroll
    for (int f = 0; f < 8; f++)
        #pragma unroll
        for (int r = 0; r < 4; r++) acc[f][r] = 0.f;

    const uint32_t aoff = (uint32_t)((w * 16 + (lane & 15)) * 144 + (lane >> 4) * 16);
    const uint32_t boff = (uint32_t)(((((lane >> 4) & 1) * 8) + (lane & 7)) * 144 + ((lane >> 3) & 1) * 16);
    const unsigned char* Bbase = g_WIe + (size_t)blockIdx.x * 6 * WIMG;

    auto issue = [&](int chunk, int buf) {
        uint32_t sb = sbase + buf * GXSTAGE;
        #pragma unroll
        for (int i = 0; i < 12; i++) {
            int idx = tid + i * 256;
            if (idx >= 2880) break;
            uint32_t dst; const unsigned char* src;
            if (idx < 2304) {
                int sp = idx / 1152; int off = (idx - sp * 1152) * 16;
                dst = sb + sp * 18432 + off;
                src = g_Xbf + (size_t)(chunk * 2 + sp) * XIMG + (size_t)m0 * 144 + off;
            } else {
                int off = (idx - 2304) * 16;
                dst = sb + 36864 + off;
                src = Bbase + (size_t)chunk * WIMG + off;
            }
            cpasync16(dst, src);
        }
        CP_COMMIT();
    };

    issue(0, 0); issue(1, 1);
    #pragma unroll 1
    for (int c = 0; c < 6; c++) {
        if (c < 5) { CP_WAIT(1); } else { CP_WAIT(0); }
        __syncthreads();
        uint32_t st = sbase + (c & 1) * GXSTAGE;
        uint32_t sAhi = st, sAlo = st + 18432, sW = st + 36864;
        #pragma unroll
        for (int kf = 0; kf < 4; kf++) {
            uint32_t ah[4], al[4], bh[4][4];
            ldsm4(ah, sAhi + aoff + kf * 32);
            ldsm4(al, sAlo + aoff + kf * 32);
            #pragma unroll
            for (int ng = 0; ng < 4; ng++)
                ldsm4(bh[ng], sW + boff + ng * 2304 + kf * 32);
            #pragma unroll
            for (int ng = 0; ng < 4; ng++) { mma16816(acc[2*ng], ah, bh[ng]); mma16816(acc[2*ng+1], ah, bh[ng]+2); }
            #pragma unroll
            for (int ng = 0; ng < 4; ng++) { mma16816(acc[2*ng], al, bh[ng]); mma16816(acc[2*ng+1], al, bh[ng]+2); }
        }
        __syncthreads();
        if (c + 2 < 6) issue(c + 2, c & 1);
    }
    #pragma unroll
    for (int f = 0; f < 8; f++) {
        int n = n0 + (f >> 1) * 16 + (f & 1) * 8 + (lane & 3) * 2;
        #pragma unroll
        for (int rowi = 0; rowi < 2; rowi++) {
            int m = m0 + w * 16 + (lane >> 2) + rowi * 8;
            *(float2*)&g_Gx[(size_t)m * G4 + n] = make_float2(acc[f][rowi*2], acc[f][rowi*2+1]);
        }
    }
}

// ---------------- persistent LSTM (2-term f16) ---------------------------------
#define WCACHE_B 73728
#define ABUF_B   18432
#define PERSIST_SMEM (WCACHE_B + 3*ABUF_B)     // 129024

__global__ void __launch_bounds__(256, 1) persist_kernel(const float* __restrict__ gx,
                                                         const float* __restrict__ benc,
                                                         const float* __restrict__ bd) {
    extern __shared__ unsigned char smem[];
    const int tid = threadIdx.x;
    const int w = tid >> 5, lane = tid & 31;
    const int wr = w & 3, wc = w >> 2;
    const int ntile = blockIdx.x, mq = blockIdx.y;
    uint32_t sbase = smem_u32(smem);
    uint32_t Wc = sbase;
    uint32_t Ab = sbase + WCACHE_B;

    const uint32_t aoff = (uint32_t)((wr * 16 + (lane & 15)) * 144 + (lane >> 4) * 16);
    const uint32_t boff = (uint32_t)((wc * 32 + ((lane >> 4) & 1) * 8 + (lane & 7)) * 144 + ((lane >> 3) & 1) * 16);

    const unsigned char* WEsrc = g_WTe + (size_t)(ntile * 8) * WIMG;
    const unsigned char* WDsrc = g_WTd + (size_t)(ntile * 8) * WIMG;

    auto loadW = [&](const unsigned char* src) {
        #pragma unroll 4
        for (int i = 0; i < 18; i++) {
            int idx = tid + i * 256;            // 0..4607
            int img = idx / 576;
            int off = (idx - img * 576) * 16;
            cpasync16(Wc + img * 9216 + off, src + (size_t)img * WIMG + off);
        }
        CP_COMMIT();
    };
    auto loadA = [&](const unsigned char* Apar, int chunk, int buf) {
        #pragma unroll
        for (int i = 0; i < 5; i++) {
            int idx = tid + i * 256;
            if (idx < 1152) {
                int split = idx / 576;
                int off = (idx - split * 576) * 16;
                cpasync16(Ab + buf * ABUF_B + split * 9216 + off,
                          Apar + (size_t)(chunk * 2 + split) * AIMG + mq * 9216 + off);
            }
        }
        CP_COMMIT();
    };

    const int j0 = ntile * 16 + wc * 8 + (lane & 3) * 2;
    const int bbase = mq * 64 + wr * 16 + (lane >> 2);
    const int chunkA = ntile >> 2;
    const size_t colOff = (size_t)((ntile & 3) * 16 + wc * 8 + (lane & 3) * 2) * 2;

    float bi[4][2];
    #pragma unroll
    for (int g = 0; g < 4; g++) { bi[g][0] = benc[g * DM + j0]; bi[g][1] = benc[g * DM + j0 + 1]; }
    float creg[4] = {0.f, 0.f, 0.f, 0.f};

    loadW(WEsrc);
    CP_WAIT(0);
    __syncthreads();

    for (int s = 0; s < NSTEP; s++) {
        const bool enc = (s < TSEQ);
        if (s == TSEQ) {
            __syncthreads();
            loadW(WDsrc);
            #pragma unroll
            for (int g = 0; g < 4; g++) { bi[g][0] = bd[g * DM + j0]; bi[g][1] = bd[g * DM + j0 + 1]; }
            CP_WAIT(0);
            __syncthreads();
        }
        const int par = s & 1;
        const unsigned char* Apar = g_Hbf + (size_t)(par * 16) * AIMG;

        float pr[16];
        if (enc) {
            #pragma unroll
            for (int rowi = 0; rowi < 2; rowi++) {
                const float* gr = gx + ((size_t)(bbase + rowi * 8) * TSEQ + s) * G4;
                #pragma unroll
                for (int g = 0; g < 4; g++) {
                    float2 v = *(const float2*)&gr[g * DM + j0];
                    pr[rowi * 8 + g * 2]     = v.x;
                    pr[rowi * 8 + g * 2 + 1] = v.y;
                }
            }
        }

        float acc[4][4];
        #pragma unroll
        for (int g = 0; g < 4; g++)
            #pragma unroll
            for (int r = 0; r < 4; r++) acc[g][r] = 0.f;

        if (s > 0) {
            loadA(Apar, 0, 0);
            loadA(Apar, 1, 1);
            #pragma unroll 1
            for (int c = 0; c < 8; c++) {
                if (c + 2 < 8) { loadA(Apar, c + 2, (c + 2) % 3); CP_WAIT(2); }
                else if (c == 6) { CP_WAIT(1); }
                else if (c == 7) { CP_WAIT(0); }
                __syncthreads();
                uint32_t at = Ab + (c % 3) * ABUF_B;
                uint32_t sAhi = at, sAlo = at + 9216;
                uint32_t wt = Wc + c * 9216;
                #pragma unroll
                for (int kf = 0; kf < 4; kf++) {
                    uint32_t ah[4], al[4], b0[4], b1[4];
                    ldsm4(ah, sAhi + aoff + kf * 32);
                    ldsm4(al, sAlo + aoff + kf * 32);
                    ldsm4(b0, wt + boff + kf * 32);
                    ldsm4(b1, wt + boff + 2304 + kf * 32);
                    mma16816(acc[0], ah, b0); mma16816(acc[1], ah, b0 + 2);
                    mma16816(acc[2], ah, b1); mma16816(acc[3], ah, b1 + 2);
                    mma16816(acc[0], al, b0); mma16816(acc[1], al, b0 + 2);
                    mma16816(acc[2], al, b1); mma16816(acc[3], al, b1 + 2);
                }
                __syncthreads();
            }
        }

        // ---- epilogue ----
        unsigned char* imgHi = g_Hbf + (size_t)(((par ^ 1) * 8 + chunkA) * 2) * AIMG;
        unsigned char* imgLo = imgHi + AIMG;
        unsigned char* decHi = nullptr;
        if (s >= TSEQ - 1) {
            int d = s - (TSEQ - 1);
            decHi = g_Dbf + (size_t)((d * 8 + chunkA) * 2) * AIMG;
        }

        #pragma unroll
        for (int rowi = 0; rowi < 2; rowi++) {
            int b = bbase + rowi * 8;
            float h2[2];
            #pragma unroll
            for (int cp = 0; cp < 2; cp++) {
                float gi = acc[0][rowi * 2 + cp] + bi[0][cp];
                float gf = acc[1][rowi * 2 + cp] + bi[1][cp];
                float gg = acc[2][rowi * 2 + cp] + bi[2][cp];
                float go = acc[3][rowi * 2 + cp] + bi[3][cp];
                if (enc) {
                    gi += pr[rowi * 8 + 0 + cp];
                    gf += pr[rowi * 8 + 2 + cp];
                    gg += pr[rowi * 8 + 4 + cp];
                    go += pr[rowi * 8 + 6 + cp];
                }
                float cn = fsig(gf) * creg[rowi * 2 + cp] + fsig(gi) * ftanh(gg);
                float hn = fsig(go) * ftanh(cn);
                creg[rowi * 2 + cp] = cn;
                h2[cp] = hn;
            }
            uint32_t hw, lw;
            hfsplit2(h2[0], h2[1], hw, lw);
            size_t off = (size_t)b * 144 + colOff;
            *(uint32_t*)(imgHi + off) = hw;
            *(uint32_t*)(imgLo + off) = lw;
            if (decHi) {
                *(uint32_t*)(decHi + off) = hw;
                *(uint32_t*)(decHi + AIMG + off) = lw;
            }
        }

        if (s < NSTEP - 1) {
            __threadfence();
            __syncthreads();
            if (tid == 0) {
                unsigned* p = &g_bar2[(s * 4 + mq) * 32];
                unsigned prev = atomicAdd(p, 1u);
                if (prev != 31u) {
                    unsigned v;
                    do {
                        asm volatile("ld.acquire.gpu.u32 %0, [%1];" : "=r"(v) : "l"(p) : "memory");
                    } while (v < 32u);
                }
            }
            __syncthreads();
        }
    }
}

// ---------------- out: Y = Dbf @ Wp^T (2-term f16), denormalize ----------------
#define OSTAGE 46080
#define OUT_SMEM (2*OSTAGE)
__global__ void __launch_bounds__(256, 1) outmma_kernel(const float* __restrict__ bp,
                                                        float* __restrict__ out) {
    extern __shared__ unsigned char smem[];
    const int tid = threadIdx.x;
    const int w = tid >> 5, lane = tid & 31;
    const int ntile = blockIdx.x;
    const int mt = blockIdx.y;
    const int d = mt >> 1, half = mt & 1;
    const int m0 = half * 128;
    uint32_t sbase = smem_u32(smem);
    float acc[8][4];
    #pragma unroll
    for (int f = 0; f < 8; f++)
        #pragma unroll
        for (int r = 0; r < 4; r++) acc[f][r] = 0.f;

    const uint32_t aoff = (uint32_t)((w * 16 + (lane & 15)) * 144 + (lane >> 4) * 16);
    const uint32_t boff = (uint32_t)(((((lane >> 4) & 1) * 8) + (lane & 7)) * 144 + ((lane >> 3) & 1) * 16);
    const unsigned char* Abase = g_Dbf + (size_t)(d * 16) * AIMG;
    const unsigned char* Bbase = g_WPe + (size_t)(ntile * 8) * WIMG;

    auto issue = [&](int chunk, int buf) {
        uint32_t sb = sbase + buf * OSTAGE;
        #pragma unroll
        for (int i = 0; i < 12; i++) {
            int idx = tid + i * 256;
            if (idx >= 2880) break;
            uint32_t dst; const unsigned char* src;
            if (idx < 2304) {
                int sp = idx / 1152; int off = (idx - sp * 1152) * 16;
                dst = sb + sp * 18432 + off;
                src = Abase + (size_t)(chunk * 2 + sp) * AIMG + (size_t)m0 * 144 + off;
            } else {
                int off = (idx - 2304) * 16;
                dst = sb + 36864 + off;
                src = Bbase + (size_t)chunk * WIMG + off;
            }
            cpasync16(dst, src);
        }
        CP_COMMIT();
    };

    issue(0, 0); issue(1, 1);
    #pragma unroll 1
    for (int c = 0; c < 8; c++) {
        if (c < 7) { CP_WAIT(1); } else { CP_WAIT(0); }
        __syncthreads();
        uint32_t st = sbase + (c & 1) * OSTAGE;
        uint32_t sAhi = st, sAlo = st + 18432, sW = st + 36864;
        #pragma unroll
        for (int kf = 0; kf < 4; kf++) {
            uint32_t ah[4], al[4], bh[4][4];
            ldsm4(ah, sAhi + aoff + kf * 32);
            ldsm4(al, sAlo + aoff + kf * 32);
            #pragma unroll
            for (int ng = 0; ng < 4; ng++)
                ldsm4(bh[ng], sW + boff + ng * 2304 + kf * 32);
            #pragma unroll
            for (int ng = 0; ng < 4; ng++) { mma16816(acc[2*ng], ah, bh[ng]); mma16816(acc[2*ng+1], ah, bh[ng]+2); }
            #pragma unroll
            for (int ng = 0; ng < 4; ng++) { mma16816(acc[2*ng], al, bh[ng]); mma16816(acc[2*ng+1], al, bh[ng]+2); }
        }
        __syncthreads();
        if (c + 2 < 8) issue(c + 2, c & 1);
    }
    #pragma unroll
    for (int f = 0; f < 8; f++) {
        int gn = ntile * 64 + (f >> 1) * 16 + (f & 1) * 8 + (lane & 3) * 2;
        #pragma unroll
        for (int rowi = 0; rowi < 2; rowi++) {
            int b = m0 + w * 16 + (lane >> 2) + rowi * 8;
            #pragma unroll
            for (int cp = 0; cp < 2; cp++) {
                int n = gn + cp;
                if (n < CIN) {
                    int bc = b * CIN + n;
                    float y = acc[f][rowi * 2 + cp] + bp[n];
                    out[(size_t)b * PRED * CIN + (size_t)d * CIN + n] =
                        y * g_std[bc] + g_mean[bc];
                }
            }
        }
    }
}

// ---------------- host launcher ------------------------------------------------
extern "C" void kernel_launch(void* const* d_in, const int* in_sizes, int n_in,
                              void* d_out, int out_size) {
    const float* x   = (const float*)d_in[0];
    const float* Wih = (const float*)d_in[1];
    const float* Whh = (const float*)d_in[2];
    const float* bih = (const float*)d_in[3];
    const float* bhh = (const float*)d_in[4];
    const float* Wp  = (const float*)d_in[5];
    const float* bp  = (const float*)d_in[6];
    float* out = (float*)d_out;

    float *gx, *wd, *bd, *benc;
    unsigned char *wte, *wtd;
    cudaGetSymbolAddress((void**)&gx,   g_Gx);
    cudaGetSymbolAddress((void**)&wd,   g_Wd);
    cudaGetSymbolAddress((void**)&bd,   g_bd);
    cudaGetSymbolAddress((void**)&benc, g_benc);
    cudaGetSymbolAddress((void**)&wte,  g_WTe);
    cudaGetSymbolAddress((void**)&wtd,  g_WTd);

    cudaFuncSetAttribute(persist_kernel, cudaFuncAttributeMaxDynamicSharedMemorySize, PERSIST_SMEM);
    cudaFuncSetAttribute(gxmma_kernel, cudaFuncAttributeMaxDynamicSharedMemorySize, GX_SMEM);
    cudaFuncSetAttribute(outmma_kernel, cudaFuncAttributeMaxDynamicSharedMemorySize, OUT_SMEM);

    stats_kernel<<<(BATCH * CIN + 255) / 256, 256>>>(x);
    bias_kernel<<<(G4 + 255) / 256, 256>>>(bih, bhh, Wih, bp);
    wd_kernel<<<dim3(DM / 64, G4 / 64), 256>>>(Wih, Wp, Whh);
    xsplit_kernel<<<(BATCH * TSEQ * CIN + 255) / 256, 256>>>(x);
    wihsplit_kernel<<<dim3(6, 32), 256>>>(Wih);
    wpsplit_kernel<<<dim3(8, 6), 256>>>(Wp);
    wsplit_kernel<<<dim3(8, 32), 256>>>(Whh, wte);
    wsplit_kernel<<<dim3(8, 32), 256>>>(wd, wtd);
    init_kernel<<<((int)(sizeof(g_Hbf) / 4) + 255) / 256, 256>>>();
    gxmma_kernel<<<dim3(32, 192), 256, GX_SMEM>>>();

    persist_kernel<<<dim3(32, 4), 256, PERSIST_SMEM>>>(gx, benc, bd);

    outmma_kernel<<<dim3(6, 192), 256, OUT_SMEM>>>(bp, out);
    (void)in_sizes; (void)n_in; (void)out_size;
}

// round 16
// speedup vs baseline: 2.0562x; 1.1990x over previous
#include <cuda_runtime.h>
#include <cuda_fp16.h>
#include <math.h>
#include <stdint.h>

#define BATCH 256
#define TSEQ  96
#define PRED  96
#define CIN   321
#define DM    512
#define G4    2048
#define HD    (BATCH*DM)
#define NSTEP (TSEQ+PRED-1)

#define AIMG  36864u            // f16 image: 256 rows x 144 B per chunk
#define WIMG  9216u             // f16 W image: 64 rows x 144 B
#define XIMG  (24576u*144u)

__device__ float g_mean[BATCH*CIN];
__device__ float g_std [BATCH*CIN];
__device__ float g_istd[BATCH*CIN];
__device__ float g_Gx  [(size_t)BATCH*TSEQ*G4];
__device__ float g_Wd  [G4*DM];
__device__ float g_bd  [G4];
__device__ float g_benc[G4];
__device__ unsigned g_bar2[NSTEP*4*32];
// f16 hidden images (single): [par2][chunk8][256][72]
__device__ __align__(1024) unsigned char g_Hbf[2*8*AIMG];
// decoder hidden f16 images (single): [d96][chunk8][256][72]
__device__ __align__(1024) unsigned char g_Dbf[(size_t)96*8*AIMG];
// recurrent W images (single f16): [ntile32][chunk8][64][72]
__device__ __align__(1024) unsigned char g_WTe[32*8*WIMG];
__device__ __align__(1024) unsigned char g_WTd[32*8*WIMG];
// gx operand images: x single f16, Wih single f16
__device__ __align__(1024) unsigned char g_Xbf[6*XIMG];
__device__ __align__(1024) unsigned char g_WIe[32*6*WIMG];
// Wp single f16: [ntile6][chunk8][64][72]
__device__ __align__(1024) unsigned char g_WPe[6*8*WIMG];

__device__ __forceinline__ float sigf(float x) { return 1.f / (1.f + expf(-x)); }
__device__ __forceinline__ float fsig(float x) { return __fdividef(1.f, 1.f + __expf(-x)); }
__device__ __forceinline__ float ftanh(float x) { return __fdividef(2.f, 1.f + __expf(-2.f * x)) - 1.f; }

__device__ __forceinline__ uint32_t smem_u32(const void* p) {
    uint32_t a;
    asm("{ .reg .u64 t; cvta.to.shared.u64 t, %1; cvt.u32.u64 %0, t; }" : "=r"(a) : "l"(p));
    return a;
}
__device__ __forceinline__ void cpasync16(uint32_t dst, const void* src) {
    asm volatile("cp.async.cg.shared.global [%0], [%1], 16;" :: "r"(dst), "l"(src) : "memory");
}
#define CP_COMMIT() asm volatile("cp.async.commit_group;" ::: "memory")
#define CP_WAIT(N)  asm volatile("cp.async.wait_group %0;" :: "n"(N) : "memory")

__device__ __forceinline__ void ldsm4(uint32_t* r, uint32_t addr) {
    asm volatile("ldmatrix.sync.aligned.m8n8.x4.shared.b16 {%0,%1,%2,%3}, [%4];"
        : "=r"(r[0]), "=r"(r[1]), "=r"(r[2]), "=r"(r[3]) : "r"(addr));
}
__device__ __forceinline__ void mma16816(float* d, const uint32_t* a, const uint32_t* b) {
    asm volatile("mma.sync.aligned.m16n8k16.row.col.f32.f16.f16.f32 "
        "{%0,%1,%2,%3}, {%4,%5,%6,%7}, {%8,%9}, {%0,%1,%2,%3};"
        : "+f"(d[0]), "+f"(d[1]), "+f"(d[2]), "+f"(d[3])
        : "r"(a[0]), "r"(a[1]), "r"(a[2]), "r"(a[3]), "r"(b[0]), "r"(b[1]));
}
__device__ __forceinline__ uint32_t hpack2(float a, float b) {
    __half h0 = __float2half_rn(a), h1 = __float2half_rn(b);
    return (uint32_t)__half_as_ushort(h0) | ((uint32_t)__half_as_ushort(h1) << 16);
}

__global__ __launch_bounds__(256) void stats_kernel(const float* __restrict__ x) {
    int idx = blockIdx.x * 256 + threadIdx.x;
    if (idx >= BATCH * CIN) return;
    int b = idx / CIN, ch = idx % CIN;
    float s = 0.f, ss = 0.f;
    const float* p = x + (size_t)b * TSEQ * CIN + ch;
    #pragma unroll 4
    for (int t = 0; t < TSEQ; t++) { float v = p[t * CIN]; s += v; ss += v * v; }
    float mean = s * (1.f / TSEQ);
    float var = ss * (1.f / TSEQ) - mean * mean;
    if (var < 0.f) var = 0.f;
    float sd = sqrtf(var + 1e-5f);
    g_mean[idx] = mean; g_std[idx] = sd; g_istd[idx] = 1.f / sd;
}

__global__ __launch_bounds__(256) void bias_kernel(const float* __restrict__ bih,
                                                   const float* __restrict__ bhh,
                                                   const float* __restrict__ Wih,
                                                   const float* __restrict__ bp) {
    int n = blockIdx.x * 256 + threadIdx.x;
    if (n >= G4) return;
    float be = bih[n] + bhh[n];
    float s = 0.f;
    const float* w = Wih + (size_t)n * CIN;
    for (int j = 0; j < CIN; j++) s += w[j] * bp[j];
    g_benc[n] = be;
    g_bd[n] = be + s;
}

__global__ __launch_bounds__(256) void wd_kernel(const float* __restrict__ Wih,
                                                 const float* __restrict__ Wp,
                                                 const float* __restrict__ Whh) {
    __shared__ float As[64 * 17];
    __shared__ float Bs[16 * 65];
    int tid = threadIdx.x;
    int n0 = blockIdx.x * 64, m0 = blockIdx.y * 64;
    int tr = tid >> 4, tc = tid & 15;
    float acc[4][4] = {};
    for (int j0 = 0; j0 < CIN; j0 += 16) {
        #pragma unroll
        for (int i = 0; i < 4; i++) {
            int l = tid + 256 * i;
            int mr = l >> 4, jj = l & 15;
            int j = j0 + jj;
            As[mr * 17 + jj] = (j < CIN) ? Wih[(size_t)(m0 + mr) * CIN + j] : 0.f;
        }
        #pragma unroll
        for (int i = 0; i < 4; i++) {
            int l = tid + 256 * i;
            int jj = l >> 6, nr = l & 63;
            int j = j0 + jj;
            Bs[jj * 65 + nr] = (j < CIN) ? Wp[(size_t)j * DM + n0 + nr] : 0.f;
        }
        __syncthreads();
        #pragma unroll
        for (int jj = 0; jj < 16; jj++) {
            float a[4], bb[4];
            #pragma unroll
            for (int r = 0; r < 4; r++) a[r] = As[(tr * 4 + r) * 17 + jj];
            #pragma unroll
            for (int cc = 0; cc < 4; cc++) bb[cc] = Bs[jj * 65 + tc * 4 + cc];
            #pragma unroll
            for (int r = 0; r < 4; r++)
                #pragma unroll
                for (int cc = 0; cc < 4; cc++) acc[r][cc] += a[r] * bb[cc];
        }
        __syncthreads();
    }
    #pragma unroll
    for (int r = 0; r < 4; r++) {
        int m = m0 + tr * 4 + r;
        #pragma unroll
        for (int cc = 0; cc < 4; cc++) {
            int n = n0 + tc * 4 + cc;
            g_Wd[(size_t)m * DM + n] = Whh[(size_t)m * DM + n] + acc[r][cc];
        }
    }
}

__global__ __launch_bounds__(256) void wsplit_kernel(const float* __restrict__ src,
                                                     unsigned char* __restrict__ dst) {
    int chunk = blockIdx.x, ntile = blockIdx.y;
    int tid = threadIdx.x;
    int rr = tid >> 2, q = tid & 3;
    int joct = rr >> 5, rem = rr & 31;
    int gate = rem >> 3, j7 = rem & 7;
    int srow = gate * DM + ntile * 16 + joct * 8 + j7;
    unsigned char* d0 = dst + (size_t)(ntile * 8 + chunk) * WIMG;
    #pragma unroll
    for (int c = 0; c < 18; c++) {
        int col = q * 18 + c;
        float v = (col < 64) ? src[(size_t)srow * DM + chunk * 64 + col] : 0.f;
        *(__half*)(d0 + (size_t)rr * 144 + col * 2) = __float2half_rn(v);
    }
}

__global__ __launch_bounds__(256) void wihsplit_kernel(const float* __restrict__ Wih) {
    int chunk = blockIdx.x, ntile = blockIdx.y;
    int tid = threadIdx.x;
    int rr = tid >> 2, q = tid & 3;
    int srow = ntile * 64 + rr;
    unsigned char* d0 = g_WIe + (size_t)(ntile * 6 + chunk) * WIMG;
    #pragma unroll
    for (int c = 0; c < 18; c++) {
        int col = q * 18 + c;
        int k = chunk * 64 + col;
        float v = (col < 64 && k < CIN) ? Wih[(size_t)srow * CIN + k] : 0.f;
        *(__half*)(d0 + (size_t)rr * 144 + col * 2) = __float2half_rn(v);
    }
}

__global__ __launch_bounds__(256) void wpsplit_kernel(const float* __restrict__ Wp) {
    int chunk = blockIdx.x, ntile = blockIdx.y;
    int tid = threadIdx.x;
    int rr = tid >> 2, q = tid & 3;
    int n = ntile * 64 + rr;
    unsigned char* d0 = g_WPe + (size_t)(ntile * 8 + chunk) * WIMG;
    #pragma unroll
    for (int c = 0; c < 18; c++) {
        int col = q * 18 + c;
        int k = chunk * 64 + col;
        float v = (col < 64 && n < CIN) ? Wp[(size_t)n * DM + k] : 0.f;
        *(__half*)(d0 + (size_t)rr * 144 + col * 2) = __float2half_rn(v);
    }
}

__global__ __launch_bounds__(256) void xsplit_kernel(const float* __restrict__ x) {
    int idx = blockIdx.x * 256 + threadIdx.x;
    if (idx >= BATCH * TSEQ * CIN) return;
    int m = idx / CIN, k = idx - m * CIN;
    int b = m / TSEQ;
    int bc = b * CIN + k;
    float v = (x[idx] - g_mean[bc]) * g_istd[bc];
    int chunk = k >> 6, col = k & 63;
    size_t offh = ((size_t)chunk * 24576 + m) * 144 + col * 2;
    *(__half*)(g_Xbf + offh) = __float2half_rn(v);
}

__global__ __launch_bounds__(256) void init_kernel() {
    int i = blockIdx.x * 256 + threadIdx.x;
    if (i < (int)(sizeof(g_Hbf) / 4)) ((uint32_t*)g_Hbf)[i] = 0u;
    if (i < NSTEP * 4 * 32) g_bar2[i] = 0u;
}

// ---------------- gx = xnorm @ Wih^T, 1-term f16 -------------------------------
#define GXSTAGE 27648
#define GX_SMEM (2*GXSTAGE)
__global__ void __launch_bounds__(256, 1) gxmma_kernel() {
    extern __shared__ unsigned char smem[];
    const int tid = threadIdx.x;
    const int w = tid >> 5, lane = tid & 31;
    const int n0 = blockIdx.x * 64;
    const int m0 = blockIdx.y * 128;
    uint32_t sbase = smem_u32(smem);
    float acc[8][4];
    #pragma unroll
    for (int f = 0; f < 8; f++)
        #pragma unroll
        for (int r = 0; r < 4; r++) acc[f][r] = 0.f;

    const uint32_t aoff = (uint32_t)((w * 16 + (lane & 15)) * 144 + (lane >> 4) * 16);
    const uint32_t boff = (uint32_t)(((((lane >> 4) & 1) * 8) + (lane & 7)) * 144 + ((lane >> 3) & 1) * 16);
    const unsigned char* Bbase = g_WIe + (size_t)blockIdx.x * 6 * WIMG;

    auto issue = [&](int chunk, int buf) {
        uint32_t sb = sbase + buf * GXSTAGE;
        #pragma unroll
        for (int i = 0; i < 7; i++) {
            int idx = tid + i * 256;
            if (idx >= 1728) break;
            uint32_t dst; const unsigned char* src;
            if (idx < 1152) {
                int off = idx * 16;
                dst = sb + off;
                src = g_Xbf + (size_t)chunk * XIMG + (size_t)m0 * 144 + off;
            } else {
                int off = (idx - 1152) * 16;
                dst = sb + 18432 + off;
                src = Bbase + (size_t)chunk * WIMG + off;
            }
            cpasync16(dst, src);
        }
        CP_COMMIT();
    };

    issue(0, 0); issue(1, 1);
    #pragma unroll 1
    for (int c = 0; c < 6; c++) {
        if (c < 5) { CP_WAIT(1); } else { CP_WAIT(0); }
        __syncthreads();
        uint32_t st = sbase + (c & 1) * GXSTAGE;
        uint32_t sA = st, sW = st + 18432;
        #pragma unroll
        for (int kf = 0; kf < 4; kf++) {
            uint32_t ah[4], bh[4][4];
            ldsm4(ah, sA + aoff + kf * 32);
            #pragma unroll
            for (int ng = 0; ng < 4; ng++)
                ldsm4(bh[ng], sW + boff + ng * 2304 + kf * 32);
            #pragma unroll
            for (int ng = 0; ng < 4; ng++) { mma16816(acc[2*ng], ah, bh[ng]); mma16816(acc[2*ng+1], ah, bh[ng]+2); }
        }
        __syncthreads();
        if (c + 2 < 6) issue(c + 2, c & 1);
    }
    #pragma unroll
    for (int f = 0; f < 8; f++) {
        int n = n0 + (f >> 1) * 16 + (f & 1) * 8 + (lane & 3) * 2;
        #pragma unroll
        for (int rowi = 0; rowi < 2; rowi++) {
            int m = m0 + w * 16 + (lane >> 2) + rowi * 8;
            *(float2*)&g_Gx[(size_t)m * G4 + n] = make_float2(acc[f][rowi*2], acc[f][rowi*2+1]);
        }
    }
}

// ---------------- persistent LSTM (1-term f16) ---------------------------------
#define WCACHE_B 73728
#define ABUF_B   9216
#define PERSIST_SMEM (WCACHE_B + 3*ABUF_B)     // 101376

__global__ void __launch_bounds__(256, 1) persist_kernel(const float* __restrict__ gx,
                                                         const float* __restrict__ benc,
                                                         const float* __restrict__ bd) {
    extern __shared__ unsigned char smem[];
    const int tid = threadIdx.x;
    const int w = tid >> 5, lane = tid & 31;
    const int wr = w & 3, wc = w >> 2;
    const int ntile = blockIdx.x, mq = blockIdx.y;
    uint32_t sbase = smem_u32(smem);
    uint32_t Wc = sbase;
    uint32_t Ab = sbase + WCACHE_B;

    const uint32_t aoff = (uint32_t)((wr * 16 + (lane & 15)) * 144 + (lane >> 4) * 16);
    const uint32_t boff = (uint32_t)((wc * 32 + ((lane >> 4) & 1) * 8 + (lane & 7)) * 144 + ((lane >> 3) & 1) * 16);

    const unsigned char* WEsrc = g_WTe + (size_t)(ntile * 8) * WIMG;
    const unsigned char* WDsrc = g_WTd + (size_t)(ntile * 8) * WIMG;

    auto loadW = [&](const unsigned char* src) {
        #pragma unroll 4
        for (int i = 0; i < 18; i++) {
            int idx = tid + i * 256;
            int img = idx / 576;
            int off = (idx - img * 576) * 16;
            cpasync16(Wc + img * 9216 + off, src + (size_t)img * WIMG + off);
        }
        CP_COMMIT();
    };
    auto loadA = [&](const unsigned char* Apar, int chunk, int buf) {
        #pragma unroll
        for (int i = 0; i < 3; i++) {
            int idx = tid + i * 256;
            if (idx < 576) {
                int off = idx * 16;
                cpasync16(Ab + buf * ABUF_B + off,
                          Apar + (size_t)chunk * AIMG + mq * 9216 + off);
            }
        }
        CP_COMMIT();
    };

    const int j0 = ntile * 16 + wc * 8 + (lane & 3) * 2;
    const int bbase = mq * 64 + wr * 16 + (lane >> 2);
    const int chunkA = ntile >> 2;
    const size_t colOff = (size_t)((ntile & 3) * 16 + wc * 8 + (lane & 3) * 2) * 2;

    float bi[4][2];
    #pragma unroll
    for (int g = 0; g < 4; g++) { bi[g][0] = benc[g * DM + j0]; bi[g][1] = benc[g * DM + j0 + 1]; }
    float creg[4] = {0.f, 0.f, 0.f, 0.f};

    loadW(WEsrc);
    CP_WAIT(0);
    __syncthreads();

    for (int s = 0; s < NSTEP; s++) {
        const bool enc = (s < TSEQ);
        if (s == TSEQ) {
            __syncthreads();
            loadW(WDsrc);
            #pragma unroll
            for (int g = 0; g < 4; g++) { bi[g][0] = bd[g * DM + j0]; bi[g][1] = bd[g * DM + j0 + 1]; }
            CP_WAIT(0);
            __syncthreads();
        }
        const int par = s & 1;
        const unsigned char* Apar = g_Hbf + (size_t)(par * 8) * AIMG;

        float pr[16];
        if (enc) {
            #pragma unroll
            for (int rowi = 0; rowi < 2; rowi++) {
                const float* gr = gx + ((size_t)(bbase + rowi * 8) * TSEQ + s) * G4;
                #pragma unroll
                for (int g = 0; g < 4; g++) {
                    float2 v = *(const float2*)&gr[g * DM + j0];
                    pr[rowi * 8 + g * 2]     = v.x;
                    pr[rowi * 8 + g * 2 + 1] = v.y;
                }
            }
        }

        float acc[4][4];
        #pragma unroll
        for (int g = 0; g < 4; g++)
            #pragma unroll
            for (int r = 0; r < 4; r++) acc[g][r] = 0.f;

        if (s > 0) {
            loadA(Apar, 0, 0);
            loadA(Apar, 1, 1);
            #pragma unroll 1
            for (int c = 0; c < 8; c++) {
                if (c + 2 < 8) { loadA(Apar, c + 2, (c + 2) % 3); CP_WAIT(2); }
                else if (c == 6) { CP_WAIT(1); }
                else if (c == 7) { CP_WAIT(0); }
                __syncthreads();
                uint32_t at = Ab + (c % 3) * ABUF_B;
                uint32_t wt = Wc + c * 9216;
                #pragma unroll
                for (int kf = 0; kf < 4; kf++) {
                    uint32_t ah[4], b0[4], b1[4];
                    ldsm4(ah, at + aoff + kf * 32);
                    ldsm4(b0, wt + boff + kf * 32);
                    ldsm4(b1, wt + boff + 2304 + kf * 32);
                    mma16816(acc[0], ah, b0); mma16816(acc[1], ah, b0 + 2);
                    mma16816(acc[2], ah, b1); mma16816(acc[3], ah, b1 + 2);
                }
                __syncthreads();
            }
        }

        // ---- epilogue ----
        unsigned char* imgH = g_Hbf + (size_t)((par ^ 1) * 8 + chunkA) * AIMG;
        unsigned char* decH = nullptr;
        if (s >= TSEQ - 1) {
            int d = s - (TSEQ - 1);
            decH = g_Dbf + (size_t)(d * 8 + chunkA) * AIMG;
        }

        #pragma unroll
        for (int rowi = 0; rowi < 2; rowi++) {
            int b = bbase + rowi * 8;
            float h2[2];
            #pragma unroll
            for (int cp = 0; cp < 2; cp++) {
                float gi = acc[0][rowi * 2 + cp] + bi[0][cp];
                float gf = acc[1][rowi * 2 + cp] + bi[1][cp];
                float gg = acc[2][rowi * 2 + cp] + bi[2][cp];
                float go = acc[3][rowi * 2 + cp] + bi[3][cp];
                if (enc) {
                    gi += pr[rowi * 8 + 0 + cp];
                    gf += pr[rowi * 8 + 2 + cp];
                    gg += pr[rowi * 8 + 4 + cp];
                    go += pr[rowi * 8 + 6 + cp];
                }
                float cn = fsig(gf) * creg[rowi * 2 + cp] + fsig(gi) * ftanh(gg);
                float hn = fsig(go) * ftanh(cn);
                creg[rowi * 2 + cp] = cn;
                h2[cp] = hn;
            }
            uint32_t hw = hpack2(h2[0], h2[1]);
            size_t off = (size_t)b * 144 + colOff;
            *(uint32_t*)(imgH + off) = hw;
            if (decH) *(uint32_t*)(decH + off) = hw;
        }

        if (s < NSTEP - 1) {
            __threadfence();
            __syncthreads();
            if (tid == 0) {
                unsigned* p = &g_bar2[(s * 4 + mq) * 32];
                unsigned prev = atomicAdd(p, 1u);
                if (prev != 31u) {
                    unsigned v;
                    do {
                        asm volatile("ld.acquire.gpu.u32 %0, [%1];" : "=r"(v) : "l"(p) : "memory");
                    } while (v < 32u);
                }
            }
            __syncthreads();
        }
    }
}

// ---------------- out: Y = Dbf @ Wp^T (1-term f16), denormalize ----------------
#define OSTAGE 27648
#define OUT_SMEM (2*OSTAGE)
__global__ void __launch_bounds__(256, 1) outmma_kernel(const float* __restrict__ bp,
                                                        float* __restrict__ out) {
    extern __shared__ unsigned char smem[];
    const int tid = threadIdx.x;
    const int w = tid >> 5, lane = tid & 31;
    const int ntile = blockIdx.x;
    const int mt = blockIdx.y;
    const int d = mt >> 1, half = mt & 1;
    const int m0 = half * 128;
    uint32_t sbase = smem_u32(smem);
    float acc[8][4];
    #pragma unroll
    for (int f = 0; f < 8; f++)
        #pragma unroll
        for (int r = 0; r < 4; r++) acc[f][r] = 0.f;

    const uint32_t aoff = (uint32_t)((w * 16 + (lane & 15)) * 144 + (lane >> 4) * 16);
    const uint32_t boff = (uint32_t)(((((lane >> 4) & 1) * 8) + (lane & 7)) * 144 + ((lane >> 3) & 1) * 16);
    const unsigned char* Abase = g_Dbf + (size_t)(d * 8) * AIMG;
    const unsigned char* Bbase = g_WPe + (size_t)(ntile * 8) * WIMG;

    auto issue = [&](int chunk, int buf) {
        uint32_t sb = sbase + buf * OSTAGE;
        #pragma unroll
        for (int i = 0; i < 7; i++) {
            int idx = tid + i * 256;
            if (idx >= 1728) break;
            uint32_t dst; const unsigned char* src;
            if (idx < 1152) {
                int off = idx * 16;
                dst = sb + off;
                src = Abase + (size_t)chunk * AIMG + (size_t)m0 * 144 + off;
            } else {
                int off = (idx - 1152) * 16;
                dst = sb + 18432 + off;
                src = Bbase + (size_t)chunk * WIMG + off;
            }
            cpasync16(dst, src);
        }
        CP_COMMIT();
    };

    issue(0, 0); issue(1, 1);
    #pragma unroll 1
    for (int c = 0; c < 8; c++) {
        if (c < 7) { CP_WAIT(1); } else { CP_WAIT(0); }
        __syncthreads();
        uint32_t st = sbase + (c & 1) * OSTAGE;
        uint32_t sA = st, sW = st + 18432;
        #pragma unroll
        for (int kf = 0; kf < 4; kf++) {
            uint32_t ah[4], bh[4][4];
            ldsm4(ah, sA + aoff + kf * 32);
            #pragma unroll
            for (int ng = 0; ng < 4; ng++)
                ldsm4(bh[ng], sW + boff + ng * 2304 + kf * 32);
            #pragma unroll
            for (int ng = 0; ng < 4; ng++) { mma16816(acc[2*ng], ah, bh[ng]); mma16816(acc[2*ng+1], ah, bh[ng]+2); }
        }
        __syncthreads();
        if (c + 2 < 8) issue(c + 2, c & 1);
    }
    #pragma unroll
    for (int f = 0; f < 8; f++) {
        int gn = ntile * 64 + (f >> 1) * 16 + (f & 1) * 8 + (lane & 3) * 2;
        #pragma unroll
        for (int rowi = 0; rowi < 2; rowi++) {
            int b = m0 + w * 16 + (lane >> 2) + rowi * 8;
            #pragma unroll
            for (int cp = 0; cp < 2; cp++) {
                int n = gn + cp;
                if (n < CIN) {
                    int bc = b * CIN + n;
                    float y = acc[f][rowi * 2 + cp] + bp[n];
                    out[(size_t)b * PRED * CIN + (size_t)d * CIN + n] =
                        y * g_std[bc] + g_mean[bc];
                }
            }
        }
    }
}

// ---------------- host launcher ------------------------------------------------
extern "C" void kernel_launch(void* const* d_in, const int* in_sizes, int n_in,
                              void* d_out, int out_size) {
    const float* x   = (const float*)d_in[0];
    const float* Wih = (const float*)d_in[1];
    const float* Whh = (const float*)d_in[2];
    const float* bih = (const float*)d_in[3];
    const float* bhh = (const float*)d_in[4];
    const float* Wp  = (const float*)d_in[5];
    const float* bp  = (const float*)d_in[6];
    float* out = (float*)d_out;

    float *gx, *wd, *bd, *benc;
    unsigned char *wte, *wtd;
    cudaGetSymbolAddress((void**)&gx,   g_Gx);
    cudaGetSymbolAddress((void**)&wd,   g_Wd);
    cudaGetSymbolAddress((void**)&bd,   g_bd);
    cudaGetSymbolAddress((void**)&benc, g_benc);
    cudaGetSymbolAddress((void**)&wte,  g_WTe);
    cudaGetSymbolAddress((void**)&wtd,  g_WTd);

    cudaFuncSetAttribute(persist_kernel, cudaFuncAttributeMaxDynamicSharedMemorySize, PERSIST_SMEM);
    cudaFuncSetAttribute(gxmma_kernel, cudaFuncAttributeMaxDynamicSharedMemorySize, GX_SMEM);
    cudaFuncSetAttribute(outmma_kernel, cudaFuncAttributeMaxDynamicSharedMemorySize, OUT_SMEM);

    stats_kernel<<<(BATCH * CIN + 255) / 256, 256>>>(x);
    bias_kernel<<<(G4 + 255) / 256, 256>>>(bih, bhh, Wih, bp);
    wd_kernel<<<dim3(DM / 64, G4 / 64), 256>>>(Wih, Wp, Whh);
    xsplit_kernel<<<(BATCH * TSEQ * CIN + 255) / 256, 256>>>(x);
    wihsplit_kernel<<<dim3(6, 32), 256>>>(Wih);
    wpsplit_kernel<<<dim3(8, 6), 256>>>(Wp);
    wsplit_kernel<<<dim3(8, 32), 256>>>(Whh, wte);
    wsplit_kernel<<<dim3(8, 32), 256>>>(wd, wtd);
    init_kernel<<<((int)(sizeof(g_Hbf) / 4) + 255) / 256, 256>>>();
    gxmma_kernel<<<dim3(32, 192), 256, GX_SMEM>>>();

    persist_kernel<<<dim3(32, 4), 256, PERSIST_SMEM>>>(gx, benc, bd);

    outmma_kernel<<<dim3(6, 192), 256, OUT_SMEM>>>(bp, out);
    (void)in_sizes; (void)n_in; (void)out_size;
}

// round 17
// speedup vs baseline: 2.4431x; 1.1882x over previous
#include <cuda_runtime.h>
#include <cuda_fp16.h>
#include <math.h>
#include <stdint.h>

#define BATCH 256
#define TSEQ  96
#define PRED  96
#define CIN   321
#define DM    512
#define G4    2048
#define HD    (BATCH*DM)
#define NSTEP (TSEQ+PRED-1)

#define AIMG  36864u            // f16 image: 256 rows x 144 B per chunk
#define WIMG  9216u             // f16 W image: 64 rows x 144 B
#define XIMG  (24576u*144u)

__device__ float g_mean[BATCH*CIN];
__device__ float g_std [BATCH*CIN];
__device__ float g_istd[BATCH*CIN];
__device__ float g_Gx  [(size_t)BATCH*TSEQ*G4];
__device__ float g_Wd  [G4*DM];
__device__ float g_bd  [G4];
__device__ float g_benc[G4];
__device__ unsigned g_bar2[NSTEP*4*32];
// f16 hidden images (single): [par2][chunk8][256][72]
__device__ __align__(1024) unsigned char g_Hbf[2*8*AIMG];
// decoder hidden f16 images (single): [d96][chunk8][256][72]
__device__ __align__(1024) unsigned char g_Dbf[(size_t)96*8*AIMG];
// recurrent W images (single f16): [ntile32][chunk8][64][72]
__device__ __align__(1024) unsigned char g_WTe[32*8*WIMG];
__device__ __align__(1024) unsigned char g_WTd[32*8*WIMG];
// gx operand images: x single f16, Wih single f16
__device__ __align__(1024) unsigned char g_Xbf[6*XIMG];
__device__ __align__(1024) unsigned char g_WIe[32*6*WIMG];
// Wp single f16: [ntile6][chunk8][64][72]
__device__ __align__(1024) unsigned char g_WPe[6*8*WIMG];

__device__ __forceinline__ float sigf(float x) { return 1.f / (1.f + expf(-x)); }
__device__ __forceinline__ float fsig(float x) { return __fdividef(1.f, 1.f + __expf(-x)); }
__device__ __forceinline__ float ftanh(float x) { return __fdividef(2.f, 1.f + __expf(-2.f * x)) - 1.f; }

__device__ __forceinline__ uint32_t smem_u32(const void* p) {
    uint32_t a;
    asm("{ .reg .u64 t; cvta.to.shared.u64 t, %1; cvt.u32.u64 %0, t; }" : "=r"(a) : "l"(p));
    return a;
}
__device__ __forceinline__ void cpasync16(uint32_t dst, const void* src) {
    asm volatile("cp.async.cg.shared.global [%0], [%1], 16;" :: "r"(dst), "l"(src) : "memory");
}
#define CP_COMMIT() asm volatile("cp.async.commit_group;" ::: "memory")
#define CP_WAIT(N)  asm volatile("cp.async.wait_group %0;" :: "n"(N) : "memory")

__device__ __forceinline__ void ldsm4(uint32_t* r, uint32_t addr) {
    asm volatile("ldmatrix.sync.aligned.m8n8.x4.shared.b16 {%0,%1,%2,%3}, [%4];"
        : "=r"(r[0]), "=r"(r[1]), "=r"(r[2]), "=r"(r[3]) : "r"(addr));
}
__device__ __forceinline__ void mma16816(float* d, const uint32_t* a, const uint32_t* b) {
    asm volatile("mma.sync.aligned.m16n8k16.row.col.f32.f16.f16.f32 "
        "{%0,%1,%2,%3}, {%4,%5,%6,%7}, {%8,%9}, {%0,%1,%2,%3};"
        : "+f"(d[0]), "+f"(d[1]), "+f"(d[2]), "+f"(d[3])
        : "r"(a[0]), "r"(a[1]), "r"(a[2]), "r"(a[3]), "r"(b[0]), "r"(b[1]));
}
__device__ __forceinline__ uint32_t hpack2(float a, float b) {
    __half h0 = __float2half_rn(a), h1 = __float2half_rn(b);
    return (uint32_t)__half_as_ushort(h0) | ((uint32_t)__half_as_ushort(h1) << 16);
}

__global__ __launch_bounds__(256) void stats_kernel(const float* __restrict__ x) {
    int idx = blockIdx.x * 256 + threadIdx.x;
    if (idx >= BATCH * CIN) return;
    int b = idx / CIN, ch = idx % CIN;
    float s = 0.f, ss = 0.f;
    const float* p = x + (size_t)b * TSEQ * CIN + ch;
    #pragma unroll 4
    for (int t = 0; t < TSEQ; t++) { float v = p[t * CIN]; s += v; ss += v * v; }
    float mean = s * (1.f / TSEQ);
    float var = ss * (1.f / TSEQ) - mean * mean;
    if (var < 0.f) var = 0.f;
    float sd = sqrtf(var + 1e-5f);
    g_mean[idx] = mean; g_std[idx] = sd; g_istd[idx] = 1.f / sd;
}

__global__ __launch_bounds__(256) void bias_kernel(const float* __restrict__ bih,
                                                   const float* __restrict__ bhh,
                                                   const float* __restrict__ Wih,
                                                   const float* __restrict__ bp) {
    int n = blockIdx.x * 256 + threadIdx.x;
    if (n >= G4) return;
    float be = bih[n] + bhh[n];
    float s = 0.f;
    const float* w = Wih + (size_t)n * CIN;
    for (int j = 0; j < CIN; j++) s += w[j] * bp[j];
    g_benc[n] = be;
    g_bd[n] = be + s;
}

__global__ __launch_bounds__(256) void wd_kernel(const float* __restrict__ Wih,
                                                 const float* __restrict__ Wp,
                                                 const float* __restrict__ Whh) {
    __shared__ float As[64 * 17];
    __shared__ float Bs[16 * 65];
    int tid = threadIdx.x;
    int n0 = blockIdx.x * 64, m0 = blockIdx.y * 64;
    int tr = tid >> 4, tc = tid & 15;
    float acc[4][4] = {};
    for (int j0 = 0; j0 < CIN; j0 += 16) {
        #pragma unroll
        for (int i = 0; i < 4; i++) {
            int l = tid + 256 * i;
            int mr = l >> 4, jj = l & 15;
            int j = j0 + jj;
            As[mr * 17 + jj] = (j < CIN) ? Wih[(size_t)(m0 + mr) * CIN + j] : 0.f;
        }
        #pragma unroll
        for (int i = 0; i < 4; i++) {
            int l = tid + 256 * i;
            int jj = l >> 6, nr = l & 63;
            int j = j0 + jj;
            Bs[jj * 65 + nr] = (j < CIN) ? Wp[(size_t)j * DM + n0 + nr] : 0.f;
        }
        __syncthreads();
        #pragma unroll
        for (int jj = 0; jj < 16; jj++) {
            float a[4], bb[4];
            #pragma unroll
            for (int r = 0; r < 4; r++) a[r] = As[(tr * 4 + r) * 17 + jj];
            #pragma unroll
            for (int cc = 0; cc < 4; cc++) bb[cc] = Bs[jj * 65 + tc * 4 + cc];
            #pragma unroll
            for (int r = 0; r < 4; r++)
                #pragma unroll
                for (int cc = 0; cc < 4; cc++) acc[r][cc] += a[r] * bb[cc];
        }
        __syncthreads();
    }
    #pragma unroll
    for (int r = 0; r < 4; r++) {
        int m = m0 + tr * 4 + r;
        #pragma unroll
        for (int cc = 0; cc < 4; cc++) {
            int n = n0 + tc * 4 + cc;
            g_Wd[(size_t)m * DM + n] = Whh[(size_t)m * DM + n] + acc[r][cc];
        }
    }
}

__global__ __launch_bounds__(256) void wsplit_kernel(const float* __restrict__ src,
                                                     unsigned char* __restrict__ dst) {
    int chunk = blockIdx.x, ntile = blockIdx.y;
    int tid = threadIdx.x;
    int rr = tid >> 2, q = tid & 3;
    int joct = rr >> 5, rem = rr & 31;
    int gate = rem >> 3, j7 = rem & 7;
    int srow = gate * DM + ntile * 16 + joct * 8 + j7;
    unsigned char* d0 = dst + (size_t)(ntile * 8 + chunk) * WIMG;
    #pragma unroll
    for (int c = 0; c < 18; c++) {
        int col = q * 18 + c;
        float v = (col < 64) ? src[(size_t)srow * DM + chunk * 64 + col] : 0.f;
        *(__half*)(d0 + (size_t)rr * 144 + col * 2) = __float2half_rn(v);
    }
}

__global__ __launch_bounds__(256) void wihsplit_kernel(const float* __restrict__ Wih) {
    int chunk = blockIdx.x, ntile = blockIdx.y;
    int tid = threadIdx.x;
    int rr = tid >> 2, q = tid & 3;
    int srow = ntile * 64 + rr;
    unsigned char* d0 = g_WIe + (size_t)(ntile * 6 + chunk) * WIMG;
    #pragma unroll
    for (int c = 0; c < 18; c++) {
        int col = q * 18 + c;
        int k = chunk * 64 + col;
        float v = (col < 64 && k < CIN) ? Wih[(size_t)srow * CIN + k] : 0.f;
        *(__half*)(d0 + (size_t)rr * 144 + col * 2) = __float2half_rn(v);
    }
}

__global__ __launch_bounds__(256) void wpsplit_kernel(const float* __restrict__ Wp) {
    int chunk = blockIdx.x, ntile = blockIdx.y;
    int tid = threadIdx.x;
    int rr = tid >> 2, q = tid & 3;
    int n = ntile * 64 + rr;
    unsigned char* d0 = g_WPe + (size_t)(ntile * 8 + chunk) * WIMG;
    #pragma unroll
    for (int c = 0; c < 18; c++) {
        int col = q * 18 + c;
        int k = chunk * 64 + col;
        float v = (col < 64 && n < CIN) ? Wp[(size_t)n * DM + k] : 0.f;
        *(__half*)(d0 + (size_t)rr * 144 + col * 2) = __float2half_rn(v);
    }
}

__global__ __launch_bounds__(256) void xsplit_kernel(const float* __restrict__ x) {
    int idx = blockIdx.x * 256 + threadIdx.x;
    if (idx >= BATCH * TSEQ * CIN) return;
    int m = idx / CIN, k = idx - m * CIN;
    int b = m / TSEQ;
    int bc = b * CIN + k;
    float v = (x[idx] - g_mean[bc]) * g_istd[bc];
    int chunk = k >> 6, col = k & 63;
    size_t offh = ((size_t)chunk * 24576 + m) * 144 + col * 2;
    *(__half*)(g_Xbf + offh) = __float2half_rn(v);
}

__global__ __launch_bounds__(256) void init_kernel() {
    int i = blockIdx.x * 256 + threadIdx.x;
    if (i < (int)(sizeof(g_Hbf) / 4)) ((uint32_t*)g_Hbf)[i] = 0u;
    if (i < NSTEP * 4 * 32) g_bar2[i] = 0u;
}

// ---------------- gx = xnorm @ Wih^T, 1-term f16 -------------------------------
#define GXSTAGE 27648
#define GX_SMEM (2*GXSTAGE)
__global__ void __launch_bounds__(256, 1) gxmma_kernel() {
    extern __shared__ unsigned char smem[];
    const int tid = threadIdx.x;
    const int w = tid >> 5, lane = tid & 31;
    const int n0 = blockIdx.x * 64;
    const int m0 = blockIdx.y * 128;
    uint32_t sbase = smem_u32(smem);
    float acc[8][4];
    #pragma unroll
    for (int f = 0; f < 8; f++)
        #pragma unroll
        for (int r = 0; r < 4; r++) acc[f][r] = 0.f;

    const uint32_t aoff = (uint32_t)((w * 16 + (lane & 15)) * 144 + (lane >> 4) * 16);
    const uint32_t boff = (uint32_t)(((((lane >> 4) & 1) * 8) + (lane & 7)) * 144 + ((lane >> 3) & 1) * 16);
    const unsigned char* Bbase = g_WIe + (size_t)blockIdx.x * 6 * WIMG;

    auto issue = [&](int chunk, int buf) {
        uint32_t sb = sbase + buf * GXSTAGE;
        #pragma unroll
        for (int i = 0; i < 7; i++) {
            int idx = tid + i * 256;
            if (idx >= 1728) break;
            uint32_t dst; const unsigned char* src;
            if (idx < 1152) {
                int off = idx * 16;
                dst = sb + off;
                src = g_Xbf + (size_t)chunk * XIMG + (size_t)m0 * 144 + off;
            } else {
                int off = (idx - 1152) * 16;
                dst = sb + 18432 + off;
                src = Bbase + (size_t)chunk * WIMG + off;
            }
            cpasync16(dst, src);
        }
        CP_COMMIT();
    };

    issue(0, 0); issue(1, 1);
    #pragma unroll 1
    for (int c = 0; c < 6; c++) {
        if (c < 5) { CP_WAIT(1); } else { CP_WAIT(0); }
        __syncthreads();
        uint32_t st = sbase + (c & 1) * GXSTAGE;
        uint32_t sA = st, sW = st + 18432;
        #pragma unroll
        for (int kf = 0; kf < 4; kf++) {
            uint32_t ah[4], bh[4][4];
            ldsm4(ah, sA + aoff + kf * 32);
            #pragma unroll
            for (int ng = 0; ng < 4; ng++)
                ldsm4(bh[ng], sW + boff + ng * 2304 + kf * 32);
            #pragma unroll
            for (int ng = 0; ng < 4; ng++) { mma16816(acc[2*ng], ah, bh[ng]); mma16816(acc[2*ng+1], ah, bh[ng]+2); }
        }
        __syncthreads();
        if (c + 2 < 6) issue(c + 2, c & 1);
    }
    #pragma unroll
    for (int f = 0; f < 8; f++) {
        int n = n0 + (f >> 1) * 16 + (f & 1) * 8 + (lane & 3) * 2;
        #pragma unroll
        for (int rowi = 0; rowi < 2; rowi++) {
            int m = m0 + w * 16 + (lane >> 2) + rowi * 8;
            *(float2*)&g_Gx[(size_t)m * G4 + n] = make_float2(acc[f][rowi*2], acc[f][rowi*2+1]);
        }
    }
}

// ---------------- persistent LSTM (1-term f16, flat A buffer) ------------------
#define WCACHE_B 73728
#define ABUF_B   73728
#define PERSIST_SMEM (WCACHE_B + ABUF_B)       // 147456

__global__ void __launch_bounds__(256, 1) persist_kernel(const float* __restrict__ gx,
                                                         const float* __restrict__ benc,
                                                         const float* __restrict__ bd) {
    extern __shared__ unsigned char smem[];
    const int tid = threadIdx.x;
    const int w = tid >> 5, lane = tid & 31;
    const int wr = w & 3, wc = w >> 2;
    const int ntile = blockIdx.x, mq = blockIdx.y;
    uint32_t sbase = smem_u32(smem);
    uint32_t Wc = sbase;
    uint32_t Ab = sbase + WCACHE_B;

    const uint32_t aoff = (uint32_t)((wr * 16 + (lane & 15)) * 144 + (lane >> 4) * 16);
    const uint32_t boff = (uint32_t)((wc * 32 + ((lane >> 4) & 1) * 8 + (lane & 7)) * 144 + ((lane >> 3) & 1) * 16);

    const unsigned char* WEsrc = g_WTe + (size_t)(ntile * 8) * WIMG;
    const unsigned char* WDsrc = g_WTd + (size_t)(ntile * 8) * WIMG;

    auto loadW = [&](const unsigned char* src) {
        #pragma unroll 4
        for (int i = 0; i < 18; i++) {
            int idx = tid + i * 256;
            int img = idx / 576;
            int off = (idx - img * 576) * 16;
            cpasync16(Wc + img * 9216 + off, src + (size_t)img * WIMG + off);
        }
        CP_COMMIT();
    };
    auto loadAchunk = [&](const unsigned char* Apar, int chunk) {
        #pragma unroll
        for (int i = 0; i < 3; i++) {
            int idx = tid + i * 256;
            if (idx < 576) {
                int off = idx * 16;
                cpasync16(Ab + chunk * 9216 + off,
                          Apar + (size_t)chunk * AIMG + mq * 9216 + off);
            }
        }
        CP_COMMIT();
    };

    const int j0 = ntile * 16 + wc * 8 + (lane & 3) * 2;
    const int bbase = mq * 64 + wr * 16 + (lane >> 2);
    const int chunkA = ntile >> 2;
    const size_t colOff = (size_t)((ntile & 3) * 16 + wc * 8 + (lane & 3) * 2) * 2;

    float bi[4][2];
    #pragma unroll
    for (int g = 0; g < 4; g++) { bi[g][0] = benc[g * DM + j0]; bi[g][1] = benc[g * DM + j0 + 1]; }
    float creg[4] = {0.f, 0.f, 0.f, 0.f};

    loadW(WEsrc);
    CP_WAIT(0);
    __syncthreads();

    for (int s = 0; s < NSTEP; s++) {
        const bool enc = (s < TSEQ);
        if (s == TSEQ) {
            __syncthreads();
            loadW(WDsrc);
            #pragma unroll
            for (int g = 0; g < 4; g++) { bi[g][0] = bd[g * DM + j0]; bi[g][1] = bd[g * DM + j0 + 1]; }
            CP_WAIT(0);
            __syncthreads();
        }
        const int par = s & 1;
        const unsigned char* Apar = g_Hbf + (size_t)(par * 8) * AIMG;

        // issue ALL 8 A-chunk groups up front (max MLP)
        if (s > 0) {
            #pragma unroll
            for (int c = 0; c < 8; c++) loadAchunk(Apar, c);
        }

        float pr[16];
        if (enc) {
            #pragma unroll
            for (int rowi = 0; rowi < 2; rowi++) {
                const float* gr = gx + ((size_t)(bbase + rowi * 8) * TSEQ + s) * G4;
                #pragma unroll
                for (int g = 0; g < 4; g++) {
                    float2 v = *(const float2*)&gr[g * DM + j0];
                    pr[rowi * 8 + g * 2]     = v.x;
                    pr[rowi * 8 + g * 2 + 1] = v.y;
                }
            }
        }

        float acc[4][4];
        #pragma unroll
        for (int g = 0; g < 4; g++)
            #pragma unroll
            for (int r = 0; r < 4; r++) acc[g][r] = 0.f;

        if (s > 0) {
            // phase 1: chunks 0-3 (first 4 groups done), phase 2: chunks 4-7
            CP_WAIT(4);
            __syncthreads();
            #pragma unroll
            for (int c = 0; c < 4; c++) {
                uint32_t at = Ab + c * 9216;
                uint32_t wt = Wc + c * 9216;
                #pragma unroll
                for (int kf = 0; kf < 4; kf++) {
                    uint32_t ah[4], b0[4], b1[4];
                    ldsm4(ah, at + aoff + kf * 32);
                    ldsm4(b0, wt + boff + kf * 32);
                    ldsm4(b1, wt + boff + 2304 + kf * 32);
                    mma16816(acc[0], ah, b0); mma16816(acc[1], ah, b0 + 2);
                    mma16816(acc[2], ah, b1); mma16816(acc[3], ah, b1 + 2);
                }
            }
            CP_WAIT(0);
            __syncthreads();
            #pragma unroll
            for (int c = 4; c < 8; c++) {
                uint32_t at = Ab + c * 9216;
                uint32_t wt = Wc + c * 9216;
                #pragma unroll
                for (int kf = 0; kf < 4; kf++) {
                    uint32_t ah[4], b0[4], b1[4];
                    ldsm4(ah, at + aoff + kf * 32);
                    ldsm4(b0, wt + boff + kf * 32);
                    ldsm4(b1, wt + boff + 2304 + kf * 32);
                    mma16816(acc[0], ah, b0); mma16816(acc[1], ah, b0 + 2);
                    mma16816(acc[2], ah, b1); mma16816(acc[3], ah, b1 + 2);
                }
            }
        }

        // ---- epilogue ----
        unsigned char* imgH = g_Hbf + (size_t)((par ^ 1) * 8 + chunkA) * AIMG;
        unsigned char* decH = nullptr;
        if (s >= TSEQ - 1) {
            int d = s - (TSEQ - 1);
            decH = g_Dbf + (size_t)(d * 8 + chunkA) * AIMG;
        }

        #pragma unroll
        for (int rowi = 0; rowi < 2; rowi++) {
            int b = bbase + rowi * 8;
            float h2[2];
            #pragma unroll
            for (int cp = 0; cp < 2; cp++) {
                float gi = acc[0][rowi * 2 + cp] + bi[0][cp];
                float gf = acc[1][rowi * 2 + cp] + bi[1][cp];
                float gg = acc[2][rowi * 2 + cp] + bi[2][cp];
                float go = acc[3][rowi * 2 + cp] + bi[3][cp];
                if (enc) {
                    gi += pr[rowi * 8 + 0 + cp];
                    gf += pr[rowi * 8 + 2 + cp];
                    gg += pr[rowi * 8 + 4 + cp];
                    go += pr[rowi * 8 + 6 + cp];
                }
                float cn = fsig(gf) * creg[rowi * 2 + cp] + fsig(gi) * ftanh(gg);
                float hn = fsig(go) * ftanh(cn);
                creg[rowi * 2 + cp] = cn;
                h2[cp] = hn;
            }
            uint32_t hw = hpack2(h2[0], h2[1]);
            size_t off = (size_t)b * 144 + colOff;
            *(uint32_t*)(imgH + off) = hw;
            if (decH) *(uint32_t*)(decH + off) = hw;
        }

        if (s < NSTEP - 1) {
            __threadfence();
            __syncthreads();
            if (tid == 0) {
                unsigned* p = &g_bar2[(s * 4 + mq) * 32];
                unsigned prev = atomicAdd(p, 1u);
                if (prev != 31u) {
                    unsigned v;
                    do {
                        asm volatile("ld.acquire.gpu.u32 %0, [%1];" : "=r"(v) : "l"(p) : "memory");
                    } while (v < 32u);
                }
            }
            __syncthreads();
        }
    }
}

// ---------------- out: Y = Dbf @ Wp^T (1-term f16), denormalize ----------------
#define OSTAGE 27648
#define OUT_SMEM (2*OSTAGE)
__global__ void __launch_bounds__(256, 1) outmma_kernel(const float* __restrict__ bp,
                                                        float* __restrict__ out) {
    extern __shared__ unsigned char smem[];
    const int tid = threadIdx.x;
    const int w = tid >> 5, lane = tid & 31;
    const int ntile = blockIdx.x;
    const int mt = blockIdx.y;
    const int d = mt >> 1, half = mt & 1;
    const int m0 = half * 128;
    uint32_t sbase = smem_u32(smem);
    float acc[8][4];
    #pragma unroll
    for (int f = 0; f < 8; f++)
        #pragma unroll
        for (int r = 0; r < 4; r++) acc[f][r] = 0.f;

    const uint32_t aoff = (uint32_t)((w * 16 + (lane & 15)) * 144 + (lane >> 4) * 16);
    const uint32_t boff = (uint32_t)(((((lane >> 4) & 1) * 8) + (lane & 7)) * 144 + ((lane >> 3) & 1) * 16);
    const unsigned char* Abase = g_Dbf + (size_t)(d * 8) * AIMG;
    const unsigned char* Bbase = g_WPe + (size_t)(ntile * 8) * WIMG;

    auto issue = [&](int chunk, int buf) {
        uint32_t sb = sbase + buf * OSTAGE;
        #pragma unroll
        for (int i = 0; i < 7; i++) {
            int idx = tid + i * 256;
            if (idx >= 1728) break;
            uint32_t dst; const unsigned char* src;
            if (idx < 1152) {
                int off = idx * 16;
                dst = sb + off;
                src = Abase + (size_t)chunk * AIMG + (size_t)m0 * 144 + off;
            } else {
                int off = (idx - 1152) * 16;
                dst = sb + 18432 + off;
                src = Bbase + (size_t)chunk * WIMG + off;
            }
            cpasync16(dst, src);
        }
        CP_COMMIT();
    };

    issue(0, 0); issue(1, 1);
    #pragma unroll 1
    for (int c = 0; c < 8; c++) {
        if (c < 7) { CP_WAIT(1); } else { CP_WAIT(0); }
        __syncthreads();
        uint32_t st = sbase + (c & 1) * OSTAGE;
        uint32_t sA = st, sW = st + 18432;
        #pragma unroll
        for (int kf = 0; kf < 4; kf++) {
            uint32_t ah[4], bh[4][4];
            ldsm4(ah, sA + aoff + kf * 32);
            #pragma unroll
            for (int ng = 0; ng < 4; ng++)
                ldsm4(bh[ng], sW + boff + ng * 2304 + kf * 32);
            #pragma unroll
            for (int ng = 0; ng < 4; ng++) { mma16816(acc[2*ng], ah, bh[ng]); mma16816(acc[2*ng+1], ah, bh[ng]+2); }
        }
        __syncthreads();
        if (c + 2 < 8) issue(c + 2, c & 1);
    }
    #pragma unroll
    for (int f = 0; f < 8; f++) {
        int gn = ntile * 64 + (f >> 1) * 16 + (f & 1) * 8 + (lane & 3) * 2;
        #pragma unroll
        for (int rowi = 0; rowi < 2; rowi++) {
            int b = m0 + w * 16 + (lane >> 2) + rowi * 8;
            #pragma unroll
            for (int cp = 0; cp < 2; cp++) {
                int n = gn + cp;
                if (n < CIN) {
                    int bc = b * CIN + n;
                    float y = acc[f][rowi * 2 + cp] + bp[n];
                    out[(size_t)b * PRED * CIN + (size_t)d * CIN + n] =
                        y * g_std[bc] + g_mean[bc];
                }
            }
        }
    }
}

// ---------------- host launcher ------------------------------------------------
extern "C" void kernel_launch(void* const* d_in, const int* in_sizes, int n_in,
                              void* d_out, int out_size) {
    const float* x   = (const float*)d_in[0];
    const float* Wih = (const float*)d_in[1];
    const float* Whh = (const float*)d_in[2];
    const float* bih = (const float*)d_in[3];
    const float* bhh = (const float*)d_in[4];
    const float* Wp  = (const float*)d_in[5];
    const float* bp  = (const float*)d_in[6];
    float* out = (float*)d_out;

    float *gx, *wd, *bd, *benc;
    unsigned char *wte, *wtd;
    cudaGetSymbolAddress((void**)&gx,   g_Gx);
    cudaGetSymbolAddress((void**)&wd,   g_Wd);
    cudaGetSymbolAddress((void**)&bd,   g_bd);
    cudaGetSymbolAddress((void**)&benc, g_benc);
    cudaGetSymbolAddress((void**)&wte,  g_WTe);
    cudaGetSymbolAddress((void**)&wtd,  g_WTd);

    cudaFuncSetAttribute(persist_kernel, cudaFuncAttributeMaxDynamicSharedMemorySize, PERSIST_SMEM);
    cudaFuncSetAttribute(gxmma_kernel, cudaFuncAttributeMaxDynamicSharedMemorySize, GX_SMEM);
    cudaFuncSetAttribute(outmma_kernel, cudaFuncAttributeMaxDynamicSharedMemorySize, OUT_SMEM);

    stats_kernel<<<(BATCH * CIN + 255) / 256, 256>>>(x);
    bias_kernel<<<(G4 + 255) / 256, 256>>>(bih, bhh, Wih, bp);
    wd_kernel<<<dim3(DM / 64, G4 / 64), 256>>>(Wih, Wp, Whh);
    xsplit_kernel<<<(BATCH * TSEQ * CIN + 255) / 256, 256>>>(x);
    wihsplit_kernel<<<dim3(6, 32), 256>>>(Wih);
    wpsplit_kernel<<<dim3(8, 6), 256>>>(Wp);
    wsplit_kernel<<<dim3(8, 32), 256>>>(Whh, wte);
    wsplit_kernel<<<dim3(8, 32), 256>>>(wd, wtd);
    init_kernel<<<((int)(sizeof(g_Hbf) / 4) + 255) / 256, 256>>>();
    gxmma_kernel<<<dim3(32, 192), 256, GX_SMEM>>>();

    persist_kernel<<<dim3(32, 4), 256, PERSIST_SMEM>>>(gx, benc, bd);

    outmma_kernel<<<dim3(6, 192), 256, OUT_SMEM>>>(bp, out);
    (void)in_sizes; (void)n_in; (void)out_size;
}